// round 2
// baseline (speedup 1.0000x reference)
#include <cuda_runtime.h>
#include <math.h>

#define SQ   1024      // sequence length
#define DM   1024      // model dim
#define NH   16        // heads
#define HD   64        // head dim
#define NB   4         // batch
#define BH   (NB*NH)   // 64
#define ER_L 2049      // Er rows per head (2*MAX_LEN+1)

// scratch for projected q,k,v in (b,h,s,hd) layout
__device__ float g_q[(size_t)BH * SQ * HD];
__device__ float g_k[(size_t)BH * SQ * HD];
__device__ float g_v[(size_t)BH * SQ * HD];

// ---------------------------------------------------------------------------
// Projection: out[b,h,s,d] = sum_c X[b,s,c] * W[h*64+d, c] + bias[h*64+d]
// M=4096 (b*s), N=1024 (h*hd), K=1024.  64x64 tile, BK=16, 4x4 micro-tile.
// ---------------------------------------------------------------------------
__global__ __launch_bounds__(256)
void proj_kernel(const float* __restrict__ X, const float* __restrict__ W,
                 const float* __restrict__ bias, int which) {
    float* out = (which == 0) ? g_q : (which == 1) ? g_k : g_v;
    __shared__ float Xs[16][65];
    __shared__ float Ws[16][65];
    const int tid = threadIdx.x;
    const int tx = tid & 15, ty = tid >> 4;
    const int m0 = blockIdx.y * 64;
    const int n0 = blockIdx.x * 64;
    float acc[4][4] = {};
    for (int k0 = 0; k0 < DM; k0 += 16) {
        #pragma unroll
        for (int i = 0; i < 4; i++) {
            int idx = tid + i * 256;              // 0..1023
            int m = idx >> 4, kk = idx & 15;
            Xs[kk][m] = X[(size_t)(m0 + m) * DM + k0 + kk];
            Ws[kk][m] = W[(size_t)(n0 + m) * DM + k0 + kk];
        }
        __syncthreads();
        #pragma unroll
        for (int kk = 0; kk < 16; kk++) {
            float xr[4], wr[4];
            #pragma unroll
            for (int a = 0; a < 4; a++) xr[a] = Xs[kk][ty * 4 + a];
            #pragma unroll
            for (int b = 0; b < 4; b++) wr[b] = Ws[kk][tx * 4 + b];
            #pragma unroll
            for (int a = 0; a < 4; a++)
                #pragma unroll
                for (int b = 0; b < 4; b++)
                    acc[a][b] += xr[a] * wr[b];
        }
        __syncthreads();
    }
    #pragma unroll
    for (int a = 0; a < 4; a++) {
        int m = m0 + ty * 4 + a;
        int bb = m >> 10, s = m & 1023;
        #pragma unroll
        for (int b = 0; b < 4; b++) {
            int n = n0 + tx * 4 + b;
            int h = n >> 6, d = n & 63;
            out[(size_t)((bb * NH + h) * SQ + s) * HD + d] = acc[a][b] + bias[n];
        }
    }
}

// ---------------------------------------------------------------------------
// Logits: attn_raw[b,h,i,j] = (q_i . k_j + q_i . Er[h, 1023 + j - i]) * 0.125
// Per block: 64x64 (i,j) tile. Er band for a tile spans 127 rows, all within
// [0,2046] (proved: l0 = 960 + j0 - i0 in [0, 1920], l0+126 <= 2046).
// ---------------------------------------------------------------------------
__global__ __launch_bounds__(256)
void logits_kernel(const float* __restrict__ Er, float* __restrict__ attn) {
    const int bh = blockIdx.z;
    const int h  = bh & 15;
    const int i0 = blockIdx.y * 64;
    const int j0 = blockIdx.x * 64;
    const float* qb = g_q + (size_t)bh * SQ * HD;
    const float* kb = g_k + (size_t)bh * SQ * HD;
    const float* Eh = Er + (size_t)h * ER_L * HD;
    const int l0 = 960 + j0 - i0;

    __shared__ float Qs[64][33];
    __shared__ float Ks[64][33];
    __shared__ float Es[127][33];

    const int tid = threadIdx.x;
    const int tx = tid & 15, ty = tid >> 4;
    float acc[4][4] = {};

    for (int c0 = 0; c0 < HD; c0 += 32) {
        for (int idx = tid; idx < 64 * 32; idx += 256) {
            int r = idx >> 5, kk = idx & 31;
            Qs[r][kk] = qb[(size_t)(i0 + r) * HD + c0 + kk];
            Ks[r][kk] = kb[(size_t)(j0 + r) * HD + c0 + kk];
        }
        for (int idx = tid; idx < 127 * 32; idx += 256) {
            int r = idx >> 5, kk = idx & 31;
            Es[r][kk] = Eh[(size_t)(l0 + r) * HD + c0 + kk];
        }
        __syncthreads();
        const int erow = 4 * (tx - ty) + 60;   // + (b-a+3) gives 4(tx-ty)+(b-a)+63
        #pragma unroll
        for (int kk = 0; kk < 32; kk++) {
            float qr[4], kr[4], er[7];
            #pragma unroll
            for (int a = 0; a < 4; a++) qr[a] = Qs[ty * 4 + a][kk];
            #pragma unroll
            for (int b = 0; b < 4; b++) kr[b] = Ks[tx * 4 + b][kk];
            #pragma unroll
            for (int c = 0; c < 7; c++) er[c] = Es[erow + c][kk];
            #pragma unroll
            for (int a = 0; a < 4; a++)
                #pragma unroll
                for (int b = 0; b < 4; b++)
                    acc[a][b] += qr[a] * (kr[b] + er[b - a + 3]);
        }
        __syncthreads();
    }
    #pragma unroll
    for (int a = 0; a < 4; a++) {
        int i = i0 + ty * 4 + a;
        #pragma unroll
        for (int b = 0; b < 4; b++) {
            int j = j0 + tx * 4 + b;
            attn[((size_t)bh * SQ + i) * SQ + j] = acc[a][b] * 0.125f;
        }
    }
}

// ---------------------------------------------------------------------------
// Row softmax (in place), row length 1024, one block per row, float4 per thread.
// ---------------------------------------------------------------------------
__global__ __launch_bounds__(256)
void softmax_kernel(float* __restrict__ attn) {
    const size_t row = blockIdx.x;
    float4* rp = reinterpret_cast<float4*>(attn + row * SQ);
    const int tid = threadIdx.x;
    __shared__ float redm[8];
    __shared__ float reds[8];
    __shared__ float fin[2];

    float4 v = rp[tid];
    float m = fmaxf(fmaxf(v.x, v.y), fmaxf(v.z, v.w));
    #pragma unroll
    for (int o = 16; o > 0; o >>= 1) m = fmaxf(m, __shfl_xor_sync(0xffffffffu, m, o));
    if ((tid & 31) == 0) redm[tid >> 5] = m;
    __syncthreads();
    if (tid == 0) {
        float t = redm[0];
        #pragma unroll
        for (int i = 1; i < 8; i++) t = fmaxf(t, redm[i]);
        fin[0] = t;
    }
    __syncthreads();
    m = fin[0];

    v.x = __expf(v.x - m);
    v.y = __expf(v.y - m);
    v.z = __expf(v.z - m);
    v.w = __expf(v.w - m);
    float s = v.x + v.y + v.z + v.w;
    #pragma unroll
    for (int o = 16; o > 0; o >>= 1) s += __shfl_xor_sync(0xffffffffu, s, o);
    if ((tid & 31) == 0) reds[tid >> 5] = s;
    __syncthreads();
    if (tid == 0) {
        float t = reds[0];
        #pragma unroll
        for (int i = 1; i < 8; i++) t += reds[i];
        fin[1] = 1.0f / t;
    }
    __syncthreads();
    const float inv = fin[1];
    v.x *= inv; v.y *= inv; v.z *= inv; v.w *= inv;
    rp[tid] = v;
}

// ---------------------------------------------------------------------------
// out[b,s, h*64+d] = sum_j attn[b,h,s,j] * v[b,h,j,d].  Per (b,h): 1024x64,
// K=1024 in chunks of 32. 64-row block, 4x4 micro-tile.
// ---------------------------------------------------------------------------
__global__ __launch_bounds__(256)
void av_kernel(const float* __restrict__ attn, float* __restrict__ out) {
    const int bh = blockIdx.y;
    const int b = bh >> 4, h = bh & 15;
    const int i0 = blockIdx.x * 64;
    const float* ab = attn + (size_t)bh * SQ * SQ;
    const float* vb = g_v + (size_t)bh * SQ * HD;

    __shared__ float As[64][33];
    __shared__ float Vs[32][65];

    const int tid = threadIdx.x;
    const int tx = tid & 15, ty = tid >> 4;
    float acc[4][4] = {};

    for (int k0 = 0; k0 < SQ; k0 += 32) {
        for (int idx = tid; idx < 64 * 32; idx += 256) {
            int r = idx >> 5, kk = idx & 31;
            As[r][kk] = ab[(size_t)(i0 + r) * SQ + k0 + kk];
        }
        for (int idx = tid; idx < 32 * 64; idx += 256) {
            int kk = idx >> 6, d = idx & 63;
            Vs[kk][d] = vb[(size_t)(k0 + kk) * HD + d];
        }
        __syncthreads();
        #pragma unroll
        for (int kk = 0; kk < 32; kk++) {
            float ar[4], vr[4];
            #pragma unroll
            for (int a = 0; a < 4; a++) ar[a] = As[ty * 4 + a][kk];
            #pragma unroll
            for (int c = 0; c < 4; c++) vr[c] = Vs[kk][tx * 4 + c];
            #pragma unroll
            for (int a = 0; a < 4; a++)
                #pragma unroll
                for (int c = 0; c < 4; c++)
                    acc[a][c] += ar[a] * vr[c];
        }
        __syncthreads();
    }
    #pragma unroll
    for (int a = 0; a < 4; a++) {
        int s = i0 + ty * 4 + a;
        #pragma unroll
        for (int c = 0; c < 4; c++) {
            int d = tx * 4 + c;
            out[((size_t)(b * SQ + s)) * DM + h * HD + d] = acc[a][c];
        }
    }
}

// ---------------------------------------------------------------------------
extern "C" void kernel_launch(void* const* d_in, const int* in_sizes, int n_in,
                              void* d_out, int out_size) {
    const float* query = (const float*)d_in[0];
    const float* key   = (const float*)d_in[1];
    const float* value = (const float*)d_in[2];
    const float* Wq    = (const float*)d_in[3];
    const float* bq    = (const float*)d_in[4];
    const float* Wk    = (const float*)d_in[5];
    const float* bk    = (const float*)d_in[6];
    const float* Wv    = (const float*)d_in[7];
    const float* bv    = (const float*)d_in[8];
    const float* Er    = (const float*)d_in[9];

    float* out  = (float*)d_out;                       // (4,1024,1024)
    float* attn = out + (size_t)NB * SQ * DM;          // (4,16,1024,1024)

    dim3 pg(16, 64);                                   // N/64, M/64
    proj_kernel<<<pg, 256>>>(query, Wq, bq, 0);
    proj_kernel<<<pg, 256>>>(key,   Wk, bk, 1);
    proj_kernel<<<pg, 256>>>(value, Wv, bv, 2);

    dim3 lg(16, 16, BH);                               // j-tiles, i-tiles, b*h
    logits_kernel<<<lg, 256>>>(Er, attn);

    softmax_kernel<<<BH * SQ, 256>>>(attn);

    dim3 ag(16, BH);                                   // i-tiles, b*h
    av_kernel<<<ag, 256>>>(attn, out);
}

// round 6
// speedup vs baseline: 1.5172x; 1.5172x over previous
#include <cuda_runtime.h>
#include <cuda_bf16.h>
#include <math.h>
#include <cstdint>

#define SQ   1024
#define DM   1024
#define NH   16
#define HD   64
#define NB   4
#define BH   (NB*NH)
#define ER_L 2049

// ---------------------------------------------------------------------------
// Device scratch
// ---------------------------------------------------------------------------
__device__ float g_q[(size_t)BH * SQ * HD];
__device__ float g_k[(size_t)BH * SQ * HD];
__device__ float g_v[(size_t)BH * SQ * HD];

__device__ __nv_bfloat16 g_xh[3][(size_t)NB * SQ * DM];   // inputs hi
__device__ __nv_bfloat16 g_xl[3][(size_t)NB * SQ * DM];   // inputs lo
__device__ __nv_bfloat16 g_wh[3][(size_t)DM * DM];        // weights hi
__device__ __nv_bfloat16 g_wl[3][(size_t)DM * DM];        // weights lo

// ---------------------------------------------------------------------------
// mma.sync helpers (base-ISA tensor core path; works on plain sm_103 target)
// ---------------------------------------------------------------------------
__device__ __forceinline__ uint32_t smem_u32(const void* p) {
    uint32_t a;
    asm("{ .reg .u64 t; cvta.to.shared.u64 t, %1; cvt.u32.u64 %0, t; }"
        : "=r"(a) : "l"(p));
    return a;
}
__device__ __forceinline__ void ldsm_x4(uint32_t (&r)[4], uint32_t addr) {
    asm volatile("ldmatrix.sync.aligned.m8n8.x4.shared.b16 {%0,%1,%2,%3}, [%4];"
                 : "=r"(r[0]), "=r"(r[1]), "=r"(r[2]), "=r"(r[3]) : "r"(addr));
}
__device__ __forceinline__ void mma_bf16(float (&c)[4], const uint32_t (&a)[4],
                                         const uint32_t b0, const uint32_t b1) {
    asm volatile("mma.sync.aligned.m16n8k16.row.col.f32.bf16.bf16.f32 "
                 "{%0,%1,%2,%3}, {%4,%5,%6,%7}, {%8,%9}, {%0,%1,%2,%3};"
                 : "+f"(c[0]), "+f"(c[1]), "+f"(c[2]), "+f"(c[3])
                 : "r"(a[0]), "r"(a[1]), "r"(a[2]), "r"(a[3]), "r"(b0), "r"(b1));
}

// ---------------------------------------------------------------------------
// fp32 -> bf16 hi/lo split (vectorized: 4 floats / thread)
// ---------------------------------------------------------------------------
__global__ __launch_bounds__(256)
void split_kernel(const float* __restrict__ src, int which, int isW, int n4) {
    int i = blockIdx.x * blockDim.x + threadIdx.x;
    if (i >= n4) return;
    __nv_bfloat16* hi = isW ? g_wh[which] : g_xh[which];
    __nv_bfloat16* lo = isW ? g_wl[which] : g_xl[which];
    float4 v = reinterpret_cast<const float4*>(src)[i];
    union { __nv_bfloat16 b[4]; uint2 u; } H, L;
    H.b[0] = __float2bfloat16(v.x);
    H.b[1] = __float2bfloat16(v.y);
    H.b[2] = __float2bfloat16(v.z);
    H.b[3] = __float2bfloat16(v.w);
    L.b[0] = __float2bfloat16(v.x - __bfloat162float(H.b[0]));
    L.b[1] = __float2bfloat16(v.y - __bfloat162float(H.b[1]));
    L.b[2] = __float2bfloat16(v.z - __bfloat162float(H.b[2]));
    L.b[3] = __float2bfloat16(v.w - __bfloat162float(H.b[3]));
    reinterpret_cast<uint2*>(hi)[i] = H.u;
    reinterpret_cast<uint2*>(lo)[i] = L.u;
}

// ---------------------------------------------------------------------------
// Projection GEMM on mma.sync: out[m,n] = X[m,:]·W[n,:] + bias[n]
// M=4096, N=1024, K=1024. Block 128x128, 8 warps (2m x 4n), warp 64x32,
// BK=32. hi/lo compensation: C += Ah·Bh + Ah·Bl + Al·Bh.
// smem rows padded to 40 bf16 (80B) -> conflict-free ldmatrix.
// ---------------------------------------------------------------------------
#define PROW 40

__global__ __launch_bounds__(256, 1)
void proj_mma_kernel(int which, const float* __restrict__ bias) {
    __shared__ __nv_bfloat16 sm[4][128 * PROW];   // Ah, Al, Bh, Bl

    const __nv_bfloat16* Ah = g_xh[which];
    const __nv_bfloat16* Al = g_xl[which];
    const __nv_bfloat16* Bh = g_wh[which];
    const __nv_bfloat16* Bl = g_wl[which];
    float* out = (which == 0) ? g_q : (which == 1) ? g_k : g_v;

    const int tid = threadIdx.x;
    const int wid = tid >> 5;
    const int lid = tid & 31;
    const int wm = wid & 1;          // m half (64 rows)
    const int wn = wid >> 1;         // n quarter (32 cols)
    const int m0 = blockIdx.y * 128;
    const int n0 = blockIdx.x * 128;

    // lane-dependent ldmatrix address offsets
    const int a_row = (lid & 7) + ((lid >> 3) & 1) * 8;   // tiles 0/2: +0, 1/3: +8
    const int a_kh  = (lid >= 16) ? 8 : 0;
    const int b_n   = (lid & 7) + ((lid >= 16) ? 8 : 0);  // tiles 2/3: n+8
    const int b_kh  = ((lid >> 3) & 1) * 8;               // tiles 1/3: k+8

    const uint32_t sA_h = smem_u32(sm[0]);
    const uint32_t sA_l = smem_u32(sm[1]);
    const uint32_t sB_h = smem_u32(sm[2]);
    const uint32_t sB_l = smem_u32(sm[3]);

    float acc[4][4][4] = {};   // [mi][ni][4]

    for (int c = 0; c < DM / 32; ++c) {
        const int k0g = c * 32;
        // load 4 planes: 128 rows x 32 bf16 each
        #pragma unroll
        for (int p = 0; p < 4; ++p) {
            const __nv_bfloat16* g = (p == 0) ? Ah : (p == 1) ? Al : (p == 2) ? Bh : Bl;
            const int rbase = (p < 2) ? m0 : n0;
            #pragma unroll
            for (int it = 0; it < 4; ++it) {
                int idx = tid + it * 256;          // 0..1023
                int r = idx >> 3, seg = idx & 7;   // seg: 4 bf16 = 8B
                uint2 v = *reinterpret_cast<const uint2*>(
                    g + (size_t)(rbase + r) * DM + k0g + seg * 4);
                *reinterpret_cast<uint2*>(&sm[p][r * PROW + seg * 4]) = v;
            }
        }
        __syncthreads();

        #pragma unroll
        for (int ks = 0; ks < 2; ++ks) {
            const int k0 = ks * 16;
            uint32_t fAh[4][4], fAl[4][4], fBh[4][2], fBl[4][2];
            #pragma unroll
            for (int mi = 0; mi < 4; ++mi) {
                uint32_t off = (uint32_t)(((wm * 64 + mi * 16 + a_row) * PROW
                                           + k0 + a_kh) * 2);
                ldsm_x4(fAh[mi], sA_h + off);
                ldsm_x4(fAl[mi], sA_l + off);
            }
            #pragma unroll
            for (int pp = 0; pp < 2; ++pp) {
                uint32_t off = (uint32_t)(((wn * 32 + pp * 16 + b_n) * PROW
                                           + k0 + b_kh) * 2);
                uint32_t t[4];
                ldsm_x4(t, sB_h + off);
                fBh[pp * 2][0] = t[0]; fBh[pp * 2][1] = t[1];
                fBh[pp * 2 + 1][0] = t[2]; fBh[pp * 2 + 1][1] = t[3];
                ldsm_x4(t, sB_l + off);
                fBl[pp * 2][0] = t[0]; fBl[pp * 2][1] = t[1];
                fBl[pp * 2 + 1][0] = t[2]; fBl[pp * 2 + 1][1] = t[3];
            }
            #pragma unroll
            for (int mi = 0; mi < 4; ++mi)
                #pragma unroll
                for (int ni = 0; ni < 4; ++ni) {
                    mma_bf16(acc[mi][ni], fAh[mi], fBh[ni][0], fBh[ni][1]);
                    mma_bf16(acc[mi][ni], fAh[mi], fBl[ni][0], fBl[ni][1]);
                    mma_bf16(acc[mi][ni], fAl[mi], fBh[ni][0], fBh[ni][1]);
                }
        }
        __syncthreads();
    }

    // epilogue: fragment (mi,ni): c0,c1 at row t/4, cols 2(t%4)+{0,1}; c2,c3 at row+8
    const int rq = lid >> 2, rr = (lid & 3) * 2;
    #pragma unroll
    for (int mi = 0; mi < 4; ++mi) {
        #pragma unroll
        for (int half = 0; half < 2; ++half) {
            const int m = m0 + wm * 64 + mi * 16 + rq + half * 8;
            const int bb = m >> 10, s = m & 1023;
            #pragma unroll
            for (int ni = 0; ni < 4; ++ni) {
                const int n = n0 + wn * 32 + ni * 8 + rr;
                const int h = n >> 6, d = n & 63;
                float2 o;
                o.x = acc[mi][ni][half * 2 + 0] + bias[n];
                o.y = acc[mi][ni][half * 2 + 1] + bias[n + 1];
                *reinterpret_cast<float2*>(
                    &out[((size_t)((bb * NH + h) * SQ + s)) * HD + d]) = o;
            }
        }
    }
}

// ---------------------------------------------------------------------------
// Logits: attn_raw[b,h,i,j] = (q_i . k_j + q_i . Er[h, 1023 + j - i]) * 0.125
// ---------------------------------------------------------------------------
__global__ __launch_bounds__(256)
void logits_kernel(const float* __restrict__ Er, float* __restrict__ attn) {
    const int bh = blockIdx.z;
    const int h  = bh & 15;
    const int i0 = blockIdx.y * 64;
    const int j0 = blockIdx.x * 64;
    const float* qb = g_q + (size_t)bh * SQ * HD;
    const float* kb = g_k + (size_t)bh * SQ * HD;
    const float* Eh = Er + (size_t)h * ER_L * HD;
    const int l0 = 960 + j0 - i0;

    __shared__ float Qs[64][33];
    __shared__ float Ks[64][33];
    __shared__ float Es[127][33];

    const int tid = threadIdx.x;
    const int tx = tid & 15, ty = tid >> 4;
    float acc[4][4] = {};

    for (int c0 = 0; c0 < HD; c0 += 32) {
        for (int idx = tid; idx < 64 * 32; idx += 256) {
            int r = idx >> 5, kk = idx & 31;
            Qs[r][kk] = qb[(size_t)(i0 + r) * HD + c0 + kk];
            Ks[r][kk] = kb[(size_t)(j0 + r) * HD + c0 + kk];
        }
        for (int idx = tid; idx < 127 * 32; idx += 256) {
            int r = idx >> 5, kk = idx & 31;
            Es[r][kk] = Eh[(size_t)(l0 + r) * HD + c0 + kk];
        }
        __syncthreads();
        const int erow = 4 * (tx - ty) + 60;
        #pragma unroll
        for (int kk = 0; kk < 32; kk++) {
            float qr[4], kr[4], er[7];
            #pragma unroll
            for (int a = 0; a < 4; a++) qr[a] = Qs[ty * 4 + a][kk];
            #pragma unroll
            for (int b = 0; b < 4; b++) kr[b] = Ks[tx * 4 + b][kk];
            #pragma unroll
            for (int c = 0; c < 7; c++) er[c] = Es[erow + c][kk];
            #pragma unroll
            for (int a = 0; a < 4; a++)
                #pragma unroll
                for (int b = 0; b < 4; b++)
                    acc[a][b] += qr[a] * (kr[b] + er[b - a + 3]);
        }
        __syncthreads();
    }
    #pragma unroll
    for (int a = 0; a < 4; a++) {
        int i = i0 + ty * 4 + a;
        #pragma unroll
        for (int b = 0; b < 4; b++) {
            int j = j0 + tx * 4 + b;
            attn[((size_t)bh * SQ + i) * SQ + j] = acc[a][b] * 0.125f;
        }
    }
}

// ---------------------------------------------------------------------------
// Row softmax (in place)
// ---------------------------------------------------------------------------
__global__ __launch_bounds__(256)
void softmax_kernel(float* __restrict__ attn) {
    const size_t row = blockIdx.x;
    float4* rp = reinterpret_cast<float4*>(attn + row * SQ);
    const int tid = threadIdx.x;
    __shared__ float redm[8];
    __shared__ float reds[8];
    __shared__ float fin[2];

    float4 v = rp[tid];
    float m = fmaxf(fmaxf(v.x, v.y), fmaxf(v.z, v.w));
    #pragma unroll
    for (int o = 16; o > 0; o >>= 1) m = fmaxf(m, __shfl_xor_sync(0xffffffffu, m, o));
    if ((tid & 31) == 0) redm[tid >> 5] = m;
    __syncthreads();
    if (tid == 0) {
        float t = redm[0];
        #pragma unroll
        for (int i = 1; i < 8; i++) t = fmaxf(t, redm[i]);
        fin[0] = t;
    }
    __syncthreads();
    m = fin[0];

    v.x = __expf(v.x - m);
    v.y = __expf(v.y - m);
    v.z = __expf(v.z - m);
    v.w = __expf(v.w - m);
    float s = v.x + v.y + v.z + v.w;
    #pragma unroll
    for (int o = 16; o > 0; o >>= 1) s += __shfl_xor_sync(0xffffffffu, s, o);
    if ((tid & 31) == 0) reds[tid >> 5] = s;
    __syncthreads();
    if (tid == 0) {
        float t = reds[0];
        #pragma unroll
        for (int i = 1; i < 8; i++) t += reds[i];
        fin[1] = 1.0f / t;
    }
    __syncthreads();
    const float inv = fin[1];
    v.x *= inv; v.y *= inv; v.z *= inv; v.w *= inv;
    rp[tid] = v;
}

// ---------------------------------------------------------------------------
// out[b,s, h*64+d] = sum_j attn[b,h,s,j] * v[b,h,j,d]
// ---------------------------------------------------------------------------
__global__ __launch_bounds__(256)
void av_kernel(const float* __restrict__ attn, float* __restrict__ out) {
    const int bh = blockIdx.y;
    const int b = bh >> 4, h = bh & 15;
    const int i0 = blockIdx.x * 64;
    const float* ab = attn + (size_t)bh * SQ * SQ;
    const float* vb = g_v + (size_t)bh * SQ * HD;

    __shared__ float As[64][33];
    __shared__ float Vs[32][65];

    const int tid = threadIdx.x;
    const int tx = tid & 15, ty = tid >> 4;
    float acc[4][4] = {};

    for (int k0 = 0; k0 < SQ; k0 += 32) {
        for (int idx = tid; idx < 64 * 32; idx += 256) {
            int r = idx >> 5, kk = idx & 31;
            As[r][kk] = ab[(size_t)(i0 + r) * SQ + k0 + kk];
        }
        for (int idx = tid; idx < 32 * 64; idx += 256) {
            int kk = idx >> 6, d = idx & 63;
            Vs[kk][d] = vb[(size_t)(k0 + kk) * HD + d];
        }
        __syncthreads();
        #pragma unroll
        for (int kk = 0; kk < 32; kk++) {
            float ar[4], vr[4];
            #pragma unroll
            for (int a = 0; a < 4; a++) ar[a] = As[ty * 4 + a][kk];
            #pragma unroll
            for (int c = 0; c < 4; c++) vr[c] = Vs[kk][tx * 4 + c];
            #pragma unroll
            for (int a = 0; a < 4; a++)
                #pragma unroll
                for (int c = 0; c < 4; c++)
                    acc[a][c] += ar[a] * vr[c];
        }
        __syncthreads();
    }
    #pragma unroll
    for (int a = 0; a < 4; a++) {
        int s = i0 + ty * 4 + a;
        #pragma unroll
        for (int c = 0; c < 4; c++) {
            int d = tx * 4 + c;
            out[((size_t)(b * SQ + s)) * DM + h * HD + d] = acc[a][c];
        }
    }
}

// ---------------------------------------------------------------------------
extern "C" void kernel_launch(void* const* d_in, const int* in_sizes, int n_in,
                              void* d_out, int out_size) {
    const float* query = (const float*)d_in[0];
    const float* key   = (const float*)d_in[1];
    const float* value = (const float*)d_in[2];
    const float* Wq    = (const float*)d_in[3];
    const float* bq    = (const float*)d_in[4];
    const float* Wk    = (const float*)d_in[5];
    const float* bk    = (const float*)d_in[6];
    const float* Wv    = (const float*)d_in[7];
    const float* bv    = (const float*)d_in[8];
    const float* Er    = (const float*)d_in[9];

    float* out  = (float*)d_out;                       // (4,1024,1024)
    float* attn = out + (size_t)NB * SQ * DM;          // (4,16,1024,1024)

    // fp32 -> bf16 hi/lo splits
    const int xn4 = NB * SQ * DM / 4;
    const int wn4 = DM * DM / 4;
    split_kernel<<<xn4 / 256, 256>>>(query, 0, 0, xn4);
    split_kernel<<<xn4 / 256, 256>>>(key,   1, 0, xn4);
    split_kernel<<<xn4 / 256, 256>>>(value, 2, 0, xn4);
    split_kernel<<<wn4 / 256, 256>>>(Wq, 0, 1, wn4);
    split_kernel<<<wn4 / 256, 256>>>(Wk, 1, 1, wn4);
    split_kernel<<<wn4 / 256, 256>>>(Wv, 2, 1, wn4);

    // tensor-core projections (mma.sync)
    dim3 pg(DM / 128, NB * SQ / 128);                  // (8, 32)
    proj_mma_kernel<<<pg, 256>>>(0, bq);
    proj_mma_kernel<<<pg, 256>>>(1, bk);
    proj_mma_kernel<<<pg, 256>>>(2, bv);

    dim3 lg(16, 16, BH);
    logits_kernel<<<lg, 256>>>(Er, attn);

    softmax_kernel<<<BH * SQ, 256>>>(attn);

    dim3 ag(16, BH);
    av_kernel<<<ag, 256>>>(attn, out);
}

// round 8
// speedup vs baseline: 2.0734x; 1.3666x over previous
#include <cuda_runtime.h>
#include <cuda_bf16.h>
#include <math.h>
#include <cstdint>

#define SQ   1024
#define DM   1024
#define NH   16
#define HD   64
#define NB   4
#define BH   (NB*NH)
#define ER_L 2049

// ---------------------------------------------------------------------------
// Device scratch
// ---------------------------------------------------------------------------
__device__ float g_q[(size_t)BH * SQ * HD];
__device__ float g_k[(size_t)BH * SQ * HD];
__device__ float g_v[(size_t)BH * SQ * HD];

__device__ __nv_bfloat16 g_xh[3][(size_t)NB * SQ * DM];   // inputs hi
__device__ __nv_bfloat16 g_xl[3][(size_t)NB * SQ * DM];   // inputs lo
__device__ __nv_bfloat16 g_wh[3][(size_t)DM * DM];        // weights hi
__device__ __nv_bfloat16 g_wl[3][(size_t)DM * DM];        // weights lo

// ---------------------------------------------------------------------------
// mma.sync helpers (base-ISA tensor core path; works on plain sm_103 target)
// ---------------------------------------------------------------------------
__device__ __forceinline__ uint32_t smem_u32(const void* p) {
    uint32_t a;
    asm("{ .reg .u64 t; cvta.to.shared.u64 t, %1; cvt.u32.u64 %0, t; }"
        : "=r"(a) : "l"(p));
    return a;
}
__device__ __forceinline__ void ldsm_x4(uint32_t (&r)[4], uint32_t addr) {
    asm volatile("ldmatrix.sync.aligned.m8n8.x4.shared.b16 {%0,%1,%2,%3}, [%4];"
                 : "=r"(r[0]), "=r"(r[1]), "=r"(r[2]), "=r"(r[3]) : "r"(addr));
}
__device__ __forceinline__ void mma_bf16(float (&c)[4], const uint32_t (&a)[4],
                                         const uint32_t b0, const uint32_t b1) {
    asm volatile("mma.sync.aligned.m16n8k16.row.col.f32.bf16.bf16.f32 "
                 "{%0,%1,%2,%3}, {%4,%5,%6,%7}, {%8,%9}, {%0,%1,%2,%3};"
                 : "+f"(c[0]), "+f"(c[1]), "+f"(c[2]), "+f"(c[3])
                 : "r"(a[0]), "r"(a[1]), "r"(a[2]), "r"(a[3]), "r"(b0), "r"(b1));
}
__device__ __forceinline__ void f4_to_hilo(float4 v, uint2& H, uint2& L) {
    union { __nv_bfloat16 b[4]; uint2 u; } hh, ll;
    hh.b[0] = __float2bfloat16(v.x);
    hh.b[1] = __float2bfloat16(v.y);
    hh.b[2] = __float2bfloat16(v.z);
    hh.b[3] = __float2bfloat16(v.w);
    ll.b[0] = __float2bfloat16(v.x - __bfloat162float(hh.b[0]));
    ll.b[1] = __float2bfloat16(v.y - __bfloat162float(hh.b[1]));
    ll.b[2] = __float2bfloat16(v.z - __bfloat162float(hh.b[2]));
    ll.b[3] = __float2bfloat16(v.w - __bfloat162float(hh.b[3]));
    H = hh.u; L = ll.u;
}

// ---------------------------------------------------------------------------
// fp32 -> bf16 hi/lo split (vectorized: 4 floats / thread)
// ---------------------------------------------------------------------------
__global__ __launch_bounds__(256)
void split_kernel(const float* __restrict__ src, int which, int isW, int n4) {
    int i = blockIdx.x * blockDim.x + threadIdx.x;
    if (i >= n4) return;
    __nv_bfloat16* hi = isW ? g_wh[which] : g_xh[which];
    __nv_bfloat16* lo = isW ? g_wl[which] : g_xl[which];
    float4 v = reinterpret_cast<const float4*>(src)[i];
    uint2 H, L;
    f4_to_hilo(v, H, L);
    reinterpret_cast<uint2*>(hi)[i] = H;
    reinterpret_cast<uint2*>(lo)[i] = L;
}

// ---------------------------------------------------------------------------
// Projection GEMM on mma.sync (validated R6)
// ---------------------------------------------------------------------------
#define PROW 40

__global__ __launch_bounds__(256, 1)
void proj_mma_kernel(int which, const float* __restrict__ bias) {
    __shared__ __nv_bfloat16 sm[4][128 * PROW];   // Ah, Al, Bh, Bl

    const __nv_bfloat16* Ah = g_xh[which];
    const __nv_bfloat16* Al = g_xl[which];
    const __nv_bfloat16* Bh = g_wh[which];
    const __nv_bfloat16* Bl = g_wl[which];
    float* out = (which == 0) ? g_q : (which == 1) ? g_k : g_v;

    const int tid = threadIdx.x;
    const int wid = tid >> 5;
    const int lid = tid & 31;
    const int wm = wid & 1;
    const int wn = wid >> 1;
    const int m0 = blockIdx.y * 128;
    const int n0 = blockIdx.x * 128;

    const int a_row = (lid & 7) + ((lid >> 3) & 1) * 8;
    const int a_kh  = (lid >= 16) ? 8 : 0;
    const int b_n   = (lid & 7) + ((lid >= 16) ? 8 : 0);
    const int b_kh  = ((lid >> 3) & 1) * 8;

    const uint32_t sA_h = smem_u32(sm[0]);
    const uint32_t sA_l = smem_u32(sm[1]);
    const uint32_t sB_h = smem_u32(sm[2]);
    const uint32_t sB_l = smem_u32(sm[3]);

    float acc[4][4][4] = {};

    for (int c = 0; c < DM / 32; ++c) {
        const int k0g = c * 32;
        #pragma unroll
        for (int p = 0; p < 4; ++p) {
            const __nv_bfloat16* g = (p == 0) ? Ah : (p == 1) ? Al : (p == 2) ? Bh : Bl;
            const int rbase = (p < 2) ? m0 : n0;
            #pragma unroll
            for (int it = 0; it < 4; ++it) {
                int idx = tid + it * 256;
                int r = idx >> 3, seg = idx & 7;
                uint2 v = *reinterpret_cast<const uint2*>(
                    g + (size_t)(rbase + r) * DM + k0g + seg * 4);
                *reinterpret_cast<uint2*>(&sm[p][r * PROW + seg * 4]) = v;
            }
        }
        __syncthreads();

        #pragma unroll
        for (int ks = 0; ks < 2; ++ks) {
            const int k0 = ks * 16;
            uint32_t fAh[4][4], fAl[4][4], fBh[4][2], fBl[4][2];
            #pragma unroll
            for (int mi = 0; mi < 4; ++mi) {
                uint32_t off = (uint32_t)(((wm * 64 + mi * 16 + a_row) * PROW
                                           + k0 + a_kh) * 2);
                ldsm_x4(fAh[mi], sA_h + off);
                ldsm_x4(fAl[mi], sA_l + off);
            }
            #pragma unroll
            for (int pp = 0; pp < 2; ++pp) {
                uint32_t off = (uint32_t)(((wn * 32 + pp * 16 + b_n) * PROW
                                           + k0 + b_kh) * 2);
                uint32_t t[4];
                ldsm_x4(t, sB_h + off);
                fBh[pp * 2][0] = t[0]; fBh[pp * 2][1] = t[1];
                fBh[pp * 2 + 1][0] = t[2]; fBh[pp * 2 + 1][1] = t[3];
                ldsm_x4(t, sB_l + off);
                fBl[pp * 2][0] = t[0]; fBl[pp * 2][1] = t[1];
                fBl[pp * 2 + 1][0] = t[2]; fBl[pp * 2 + 1][1] = t[3];
            }
            #pragma unroll
            for (int mi = 0; mi < 4; ++mi)
                #pragma unroll
                for (int ni = 0; ni < 4; ++ni) {
                    mma_bf16(acc[mi][ni], fAh[mi], fBh[ni][0], fBh[ni][1]);
                    mma_bf16(acc[mi][ni], fAh[mi], fBl[ni][0], fBl[ni][1]);
                    mma_bf16(acc[mi][ni], fAl[mi], fBh[ni][0], fBh[ni][1]);
                }
        }
        __syncthreads();
    }

    const int rq = lid >> 2, rr = (lid & 3) * 2;
    #pragma unroll
    for (int mi = 0; mi < 4; ++mi) {
        #pragma unroll
        for (int half = 0; half < 2; ++half) {
            const int m = m0 + wm * 64 + mi * 16 + rq + half * 8;
            const int bb = m >> 10, s = m & 1023;
            #pragma unroll
            for (int ni = 0; ni < 4; ++ni) {
                const int n = n0 + wn * 32 + ni * 8 + rr;
                const int h = n >> 6, d = n & 63;
                float2 o;
                o.x = acc[mi][ni][half * 2 + 0] + bias[n];
                o.y = acc[mi][ni][half * 2 + 1] + bias[n + 1];
                *reinterpret_cast<float2*>(
                    &out[((size_t)((bb * NH + h) * SQ + s)) * HD + d]) = o;
            }
        }
    }
}

// ---------------------------------------------------------------------------
// Logits on mma.sync: 128x128 tile per block.
// Phase 1: Etil[i',t] = q_i' . Er[l0b + t], t in [0,256), two 128-chunks,
//          staged to smem fp32.
// Phase 2: S = q . k^T in registers.
// Epilogue: attn = (S + Etil[i', 127 + j' - i']) * 0.125
// ---------------------------------------------------------------------------
#define LROW 72
#define ES_STRIDE 258
#define L_SMEM (4 * 128 * LROW * 2 + 128 * ES_STRIDE * 4)   // 205824 B

__global__ __launch_bounds__(256, 1)
void logits_mma_kernel(const float* __restrict__ Er, float* __restrict__ attn) {
    extern __shared__ char lsm[];
    __nv_bfloat16* Qh = reinterpret_cast<__nv_bfloat16*>(lsm);
    __nv_bfloat16* Ql = Qh + 128 * LROW;
    __nv_bfloat16* Bh = Ql + 128 * LROW;
    __nv_bfloat16* Bl = Bh + 128 * LROW;
    float* Es = reinterpret_cast<float*>(lsm + 4 * 128 * LROW * 2);

    const int bh = blockIdx.z;
    const int h  = bh & 15;
    const int i0 = blockIdx.y * 128;
    const int j0 = blockIdx.x * 128;
    const float* qb = g_q + (size_t)bh * SQ * HD;
    const float* kb = g_k + (size_t)bh * SQ * HD;
    const float* Eh = Er + (size_t)h * ER_L * HD;
    const int l0b = 896 + j0 - i0;           // Er row for t=0; t range [0,255]

    const int tid = threadIdx.x;
    const int wid = tid >> 5;
    const int lid = tid & 31;
    const int wm = wid & 3;                  // m quarter (32 rows)
    const int wn = wid >> 2;                 // n half (64 cols)

    const int a_row = (lid & 7) + ((lid >> 3) & 1) * 8;
    const int a_kh  = (lid >= 16) ? 8 : 0;
    const int b_n   = (lid & 7) + ((lid >= 16) ? 8 : 0);
    const int b_kh  = ((lid >> 3) & 1) * 8;
    const int rq = lid >> 2, rr = (lid & 3) * 2;

    const uint32_t sQh = smem_u32(Qh), sQl = smem_u32(Ql);
    const uint32_t sBh = smem_u32(Bh), sBl = smem_u32(Bl);

    // load Q tile (128x64 fp32 -> hi/lo)
    #pragma unroll
    for (int it = 0; it < 8; ++it) {
        int idx = tid + it * 256;            // 0..2047
        int r = idx >> 4, c4 = idx & 15;
        float4 v = *reinterpret_cast<const float4*>(qb + (size_t)(i0 + r) * HD + c4 * 4);
        uint2 H, L;
        f4_to_hilo(v, H, L);
        *reinterpret_cast<uint2*>(&Qh[r * LROW + c4 * 4]) = H;
        *reinterpret_cast<uint2*>(&Ql[r * LROW + c4 * 4]) = L;
    }

    float acc[2][8][4];

    // ---- two Er chunks, then K ----
    #pragma unroll
    for (int phase = 0; phase < 3; ++phase) {
        __syncthreads();                     // prior ldsm done / Q stores done
        // load B tile
        #pragma unroll
        for (int it = 0; it < 8; ++it) {
            int idx = tid + it * 256;
            int r = idx >> 4, c4 = idx & 15;
            float4 v;
            if (phase < 2) {
                int l = l0b + phase * 128 + r;
                if (l <= 2046)
                    v = *reinterpret_cast<const float4*>(Eh + (size_t)l * HD + c4 * 4);
                else
                    v = make_float4(0.f, 0.f, 0.f, 0.f);
            } else {
                v = *reinterpret_cast<const float4*>(kb + (size_t)(j0 + r) * HD + c4 * 4);
            }
            uint2 H, L;
            f4_to_hilo(v, H, L);
            *reinterpret_cast<uint2*>(&Bh[r * LROW + c4 * 4]) = H;
            *reinterpret_cast<uint2*>(&Bl[r * LROW + c4 * 4]) = L;
        }
        __syncthreads();

        #pragma unroll
        for (int mi = 0; mi < 2; ++mi)
            #pragma unroll
            for (int ni = 0; ni < 8; ++ni)
                #pragma unroll
                for (int e = 0; e < 4; ++e) acc[mi][ni][e] = 0.f;

        #pragma unroll
        for (int ks = 0; ks < 4; ++ks) {
            const int k0 = ks * 16;
            uint32_t fAh[2][4], fAl[2][4], fBh[8][2], fBl[8][2];
            #pragma unroll
            for (int mi = 0; mi < 2; ++mi) {
                uint32_t off = (uint32_t)(((wm * 32 + mi * 16 + a_row) * LROW
                                           + k0 + a_kh) * 2);
                ldsm_x4(fAh[mi], sQh + off);
                ldsm_x4(fAl[mi], sQl + off);
            }
            #pragma unroll
            for (int pp = 0; pp < 4; ++pp) {
                uint32_t off = (uint32_t)(((wn * 64 + pp * 16 + b_n) * LROW
                                           + k0 + b_kh) * 2);
                uint32_t t4[4];
                ldsm_x4(t4, sBh + off);
                fBh[pp * 2][0] = t4[0]; fBh[pp * 2][1] = t4[1];
                fBh[pp * 2 + 1][0] = t4[2]; fBh[pp * 2 + 1][1] = t4[3];
                ldsm_x4(t4, sBl + off);
                fBl[pp * 2][0] = t4[0]; fBl[pp * 2][1] = t4[1];
                fBl[pp * 2 + 1][0] = t4[2]; fBl[pp * 2 + 1][1] = t4[3];
            }
            #pragma unroll
            for (int mi = 0; mi < 2; ++mi)
                #pragma unroll
                for (int ni = 0; ni < 8; ++ni) {
                    mma_bf16(acc[mi][ni], fAh[mi], fBh[ni][0], fBh[ni][1]);
                    mma_bf16(acc[mi][ni], fAh[mi], fBl[ni][0], fBl[ni][1]);
                    mma_bf16(acc[mi][ni], fAl[mi], fBh[ni][0], fBh[ni][1]);
                }
        }

        if (phase < 2) {
            // stage Etil chunk to smem fp32
            #pragma unroll
            for (int mi = 0; mi < 2; ++mi)
                #pragma unroll
                for (int half = 0; half < 2; ++half) {
                    const int row = wm * 32 + mi * 16 + rq + half * 8;
                    #pragma unroll
                    for (int ni = 0; ni < 8; ++ni) {
                        const int col = phase * 128 + wn * 64 + ni * 8 + rr;
                        *reinterpret_cast<float2*>(&Es[row * ES_STRIDE + col]) =
                            make_float2(acc[mi][ni][half * 2], acc[mi][ni][half * 2 + 1]);
                    }
                }
        }
    }

    // acc now holds S = q.k^T; Es fully written (sync at top of phase 2 covered
    // chunk-0 writes; chunk-1 writes are by this warp's own wm rows? No —
    // epilogue reads any t, written by same-wm warps of both wn. Sync needed:
    __syncthreads();

    #pragma unroll
    for (int mi = 0; mi < 2; ++mi)
        #pragma unroll
        for (int half = 0; half < 2; ++half) {
            const int ip = wm * 32 + mi * 16 + rq + half * 8;
            const float* EsRow = Es + (size_t)ip * ES_STRIDE + (127 - ip);
            float* arow = attn + ((size_t)bh * SQ + i0 + ip) * SQ + j0;
            #pragma unroll
            for (int ni = 0; ni < 8; ++ni) {
                const int jp = wn * 64 + ni * 8 + rr;
                float2 o;
                o.x = (acc[mi][ni][half * 2 + 0] + EsRow[jp])     * 0.125f;
                o.y = (acc[mi][ni][half * 2 + 1] + EsRow[jp + 1]) * 0.125f;
                *reinterpret_cast<float2*>(&arow[jp]) = o;
            }
        }
}

// ---------------------------------------------------------------------------
// Row softmax (in place)
// ---------------------------------------------------------------------------
__global__ __launch_bounds__(256)
void softmax_kernel(float* __restrict__ attn) {
    const size_t row = blockIdx.x;
    float4* rp = reinterpret_cast<float4*>(attn + row * SQ);
    const int tid = threadIdx.x;
    __shared__ float redm[8];
    __shared__ float reds[8];
    __shared__ float fin[2];

    float4 v = rp[tid];
    float m = fmaxf(fmaxf(v.x, v.y), fmaxf(v.z, v.w));
    #pragma unroll
    for (int o = 16; o > 0; o >>= 1) m = fmaxf(m, __shfl_xor_sync(0xffffffffu, m, o));
    if ((tid & 31) == 0) redm[tid >> 5] = m;
    __syncthreads();
    if (tid == 0) {
        float t = redm[0];
        #pragma unroll
        for (int i = 1; i < 8; i++) t = fmaxf(t, redm[i]);
        fin[0] = t;
    }
    __syncthreads();
    m = fin[0];

    v.x = __expf(v.x - m);
    v.y = __expf(v.y - m);
    v.z = __expf(v.z - m);
    v.w = __expf(v.w - m);
    float s = v.x + v.y + v.z + v.w;
    #pragma unroll
    for (int o = 16; o > 0; o >>= 1) s += __shfl_xor_sync(0xffffffffu, s, o);
    if ((tid & 31) == 0) reds[tid >> 5] = s;
    __syncthreads();
    if (tid == 0) {
        float t = reds[0];
        #pragma unroll
        for (int i = 1; i < 8; i++) t += reds[i];
        fin[1] = 1.0f / t;
    }
    __syncthreads();
    const float inv = fin[1];
    v.x *= inv; v.y *= inv; v.z *= inv; v.w *= inv;
    rp[tid] = v;
}

// ---------------------------------------------------------------------------
// av on mma.sync: out[b,s,h*64+d] = sum_j attn[b,h,s,j] * v[b,h,j,d]
// Block: 128 rows (s) x 64 cols (d) per (b,h). attn converted fp32->hi/lo
// in-kernel; v transposed into smem as B operand [d][j].
// ---------------------------------------------------------------------------
#define VROW 72

__global__ __launch_bounds__(256, 2)
void av_mma_kernel(const float* __restrict__ attn, float* __restrict__ out) {
    __shared__ __nv_bfloat16 Ph[128 * VROW], Pl[128 * VROW];
    __shared__ __nv_bfloat16 Vh[64 * VROW],  Vl[64 * VROW];

    const int bh = blockIdx.y;
    const int b = bh >> 4, h = bh & 15;
    const int i0 = blockIdx.x * 128;
    const float* ab = attn + (size_t)bh * SQ * SQ;
    const float* vb = g_v + (size_t)bh * SQ * HD;

    const int tid = threadIdx.x;
    const int wid = tid >> 5;
    const int lid = tid & 31;
    const int wm = wid & 3;                  // m quarter (32 rows)
    const int wn = wid >> 2;                 // n half (32 cols)

    const int a_row = (lid & 7) + ((lid >> 3) & 1) * 8;
    const int a_kh  = (lid >= 16) ? 8 : 0;
    const int b_n   = (lid & 7) + ((lid >= 16) ? 8 : 0);
    const int b_kh  = ((lid >> 3) & 1) * 8;
    const int rq = lid >> 2, rr = (lid & 3) * 2;

    const uint32_t sPh = smem_u32(Ph), sPl = smem_u32(Pl);
    const uint32_t sVh = smem_u32(Vh), sVl = smem_u32(Vl);

    float acc[2][4][4] = {};

    for (int c = 0; c < SQ / 64; ++c) {
        __syncthreads();
        // P tile: 128 x 64 fp32 -> hi/lo
        #pragma unroll
        for (int it = 0; it < 8; ++it) {
            int idx = tid + it * 256;        // 0..2047
            int r = idx >> 4, c4 = idx & 15;
            float4 v = *reinterpret_cast<const float4*>(
                ab + (size_t)(i0 + r) * SQ + c * 64 + c4 * 4);
            uint2 H, L;
            f4_to_hilo(v, H, L);
            *reinterpret_cast<uint2*>(&Ph[r * VROW + c4 * 4]) = H;
            *reinterpret_cast<uint2*>(&Pl[r * VROW + c4 * 4]) = L;
        }
        // V tile transposed: smem[d][j] from v[j][d]
        #pragma unroll
        for (int it = 0; it < 4; ++it) {
            int idx = tid + it * 256;        // 0..1023
            int j = idx >> 4, c4 = idx & 15; // d0 = c4*4
            float4 v = *reinterpret_cast<const float4*>(
                vb + (size_t)(c * 64 + j) * HD + c4 * 4);
            int d0 = c4 * 4;
            Vh[(d0 + 0) * VROW + j] = __float2bfloat16(v.x);
            Vh[(d0 + 1) * VROW + j] = __float2bfloat16(v.y);
            Vh[(d0 + 2) * VROW + j] = __float2bfloat16(v.z);
            Vh[(d0 + 3) * VROW + j] = __float2bfloat16(v.w);
            Vl[(d0 + 0) * VROW + j] = __float2bfloat16(v.x - __bfloat162float(Vh[(d0 + 0) * VROW + j]));
            Vl[(d0 + 1) * VROW + j] = __float2bfloat16(v.y - __bfloat162float(Vh[(d0 + 1) * VROW + j]));
            Vl[(d0 + 2) * VROW + j] = __float2bfloat16(v.z - __bfloat162float(Vh[(d0 + 2) * VROW + j]));
            Vl[(d0 + 3) * VROW + j] = __float2bfloat16(v.w - __bfloat162float(Vh[(d0 + 3) * VROW + j]));
        }
        __syncthreads();

        #pragma unroll
        for (int ks = 0; ks < 4; ++ks) {
            const int k0 = ks * 16;
            uint32_t fAh[2][4], fAl[2][4], fBh[4][2], fBl[4][2];
            #pragma unroll
            for (int mi = 0; mi < 2; ++mi) {
                uint32_t off = (uint32_t)(((wm * 32 + mi * 16 + a_row) * VROW
                                           + k0 + a_kh) * 2);
                ldsm_x4(fAh[mi], sPh + off);
                ldsm_x4(fAl[mi], sPl + off);
            }
            #pragma unroll
            for (int pp = 0; pp < 2; ++pp) {
                uint32_t off = (uint32_t)(((wn * 32 + pp * 16 + b_n) * VROW
                                           + k0 + b_kh) * 2);
                uint32_t t4[4];
                ldsm_x4(t4, sVh + off);
                fBh[pp * 2][0] = t4[0]; fBh[pp * 2][1] = t4[1];
                fBh[pp * 2 + 1][0] = t4[2]; fBh[pp * 2 + 1][1] = t4[3];
                ldsm_x4(t4, sVl + off);
                fBl[pp * 2][0] = t4[0]; fBl[pp * 2][1] = t4[1];
                fBl[pp * 2 + 1][0] = t4[2]; fBl[pp * 2 + 1][1] = t4[3];
            }
            #pragma unroll
            for (int mi = 0; mi < 2; ++mi)
                #pragma unroll
                for (int ni = 0; ni < 4; ++ni) {
                    mma_bf16(acc[mi][ni], fAh[mi], fBh[ni][0], fBh[ni][1]);
                    mma_bf16(acc[mi][ni], fAh[mi], fBl[ni][0], fBl[ni][1]);
                    mma_bf16(acc[mi][ni], fAl[mi], fBh[ni][0], fBh[ni][1]);
                }
        }
    }

    #pragma unroll
    for (int mi = 0; mi < 2; ++mi)
        #pragma unroll
        for (int half = 0; half < 2; ++half) {
            const int s = i0 + wm * 32 + mi * 16 + rq + half * 8;
            #pragma unroll
            for (int ni = 0; ni < 4; ++ni) {
                const int d = wn * 32 + ni * 8 + rr;
                float2 o;
                o.x = acc[mi][ni][half * 2 + 0];
                o.y = acc[mi][ni][half * 2 + 1];
                *reinterpret_cast<float2*>(
                    &out[((size_t)(b * SQ + s)) * DM + h * HD + d]) = o;
            }
        }
}

// ---------------------------------------------------------------------------
extern "C" void kernel_launch(void* const* d_in, const int* in_sizes, int n_in,
                              void* d_out, int out_size) {
    const float* query = (const float*)d_in[0];
    const float* key   = (const float*)d_in[1];
    const float* value = (const float*)d_in[2];
    const float* Wq    = (const float*)d_in[3];
    const float* bq    = (const float*)d_in[4];
    const float* Wk    = (const float*)d_in[5];
    const float* bk    = (const float*)d_in[6];
    const float* Wv    = (const float*)d_in[7];
    const float* bv    = (const float*)d_in[8];
    const float* Er    = (const float*)d_in[9];

    float* out  = (float*)d_out;                       // (4,1024,1024)
    float* attn = out + (size_t)NB * SQ * DM;          // (4,16,1024,1024)

    cudaFuncSetAttribute(logits_mma_kernel,
                         cudaFuncAttributeMaxDynamicSharedMemorySize, L_SMEM);

    const int xn4 = NB * SQ * DM / 4;
    const int wn4 = DM * DM / 4;
    split_kernel<<<xn4 / 256, 256>>>(query, 0, 0, xn4);
    split_kernel<<<xn4 / 256, 256>>>(key,   1, 0, xn4);
    split_kernel<<<xn4 / 256, 256>>>(value, 2, 0, xn4);
    split_kernel<<<wn4 / 256, 256>>>(Wq, 0, 1, wn4);
    split_kernel<<<wn4 / 256, 256>>>(Wk, 1, 1, wn4);
    split_kernel<<<wn4 / 256, 256>>>(Wv, 2, 1, wn4);

    dim3 pg(DM / 128, NB * SQ / 128);
    proj_mma_kernel<<<pg, 256>>>(0, bq);
    proj_mma_kernel<<<pg, 256>>>(1, bk);
    proj_mma_kernel<<<pg, 256>>>(2, bv);

    dim3 lg(SQ / 128, SQ / 128, BH);                   // (8, 8, 64)
    logits_mma_kernel<<<lg, 256, L_SMEM>>>(Er, attn);

    softmax_kernel<<<BH * SQ, 256>>>(attn);

    dim3 ag(SQ / 128, BH);                             // (8, 64)
    av_mma_kernel<<<ag, 256>>>(attn, out);
}

// round 11
// speedup vs baseline: 2.0948x; 1.0103x over previous
#include <cuda_runtime.h>
#include <cuda_bf16.h>
#include <math.h>
#include <cstdint>

#define SQ   1024
#define DM   1024
#define NH   16
#define HD   64
#define NB   4
#define BH   (NB*NH)
#define ER_L 2049

// ---------------------------------------------------------------------------
// Device scratch: projected q,k,v stored directly as bf16 hi/lo pairs.
// ---------------------------------------------------------------------------
__device__ __nv_bfloat16 g_qh[(size_t)BH * SQ * HD], g_ql[(size_t)BH * SQ * HD];
__device__ __nv_bfloat16 g_kh[(size_t)BH * SQ * HD], g_kl[(size_t)BH * SQ * HD];
__device__ __nv_bfloat16 g_vh[(size_t)BH * SQ * HD], g_vl[(size_t)BH * SQ * HD];

__device__ __nv_bfloat16 g_xh[3][(size_t)NB * SQ * DM];   // inputs hi
__device__ __nv_bfloat16 g_xl[3][(size_t)NB * SQ * DM];   // inputs lo
__device__ __nv_bfloat16 g_wh[3][(size_t)DM * DM];        // weights hi
__device__ __nv_bfloat16 g_wl[3][(size_t)DM * DM];        // weights lo

__device__ __nv_bfloat16 g_erh[(size_t)NH * ER_L * HD];   // Er hi
__device__ __nv_bfloat16 g_erl[(size_t)NH * ER_L * HD];   // Er lo

__device__ float g_rowsum[(size_t)BH * SQ];               // softmax denominators

// ---------------------------------------------------------------------------
// mma.sync helpers
// ---------------------------------------------------------------------------
__device__ __forceinline__ uint32_t smem_u32(const void* p) {
    uint32_t a;
    asm("{ .reg .u64 t; cvta.to.shared.u64 t, %1; cvt.u32.u64 %0, t; }"
        : "=r"(a) : "l"(p));
    return a;
}
__device__ __forceinline__ void ldsm_x4(uint32_t (&r)[4], uint32_t addr) {
    asm volatile("ldmatrix.sync.aligned.m8n8.x4.shared.b16 {%0,%1,%2,%3}, [%4];"
                 : "=r"(r[0]), "=r"(r[1]), "=r"(r[2]), "=r"(r[3]) : "r"(addr));
}
__device__ __forceinline__ void mma_bf16(float (&c)[4], const uint32_t (&a)[4],
                                         const uint32_t b0, const uint32_t b1) {
    asm volatile("mma.sync.aligned.m16n8k16.row.col.f32.bf16.bf16.f32 "
                 "{%0,%1,%2,%3}, {%4,%5,%6,%7}, {%8,%9}, {%0,%1,%2,%3};"
                 : "+f"(c[0]), "+f"(c[1]), "+f"(c[2]), "+f"(c[3])
                 : "r"(a[0]), "r"(a[1]), "r"(a[2]), "r"(a[3]), "r"(b0), "r"(b1));
}
__device__ __forceinline__ void f4_to_hilo(float4 v, uint2& H, uint2& L) {
    union { __nv_bfloat16 b[4]; uint2 u; } hh, ll;
    hh.b[0] = __float2bfloat16(v.x);
    hh.b[1] = __float2bfloat16(v.y);
    hh.b[2] = __float2bfloat16(v.z);
    hh.b[3] = __float2bfloat16(v.w);
    ll.b[0] = __float2bfloat16(v.x - __bfloat162float(hh.b[0]));
    ll.b[1] = __float2bfloat16(v.y - __bfloat162float(hh.b[1]));
    ll.b[2] = __float2bfloat16(v.z - __bfloat162float(hh.b[2]));
    ll.b[3] = __float2bfloat16(v.w - __bfloat162float(hh.b[3]));
    H = hh.u; L = ll.u;
}

// ---------------------------------------------------------------------------
// fp32 -> bf16 hi/lo splits
// ---------------------------------------------------------------------------
__global__ __launch_bounds__(256)
void split_kernel(const float* __restrict__ src, int which, int isW, int n4) {
    int i = blockIdx.x * blockDim.x + threadIdx.x;
    if (i >= n4) return;
    __nv_bfloat16* hi = isW ? g_wh[which] : g_xh[which];
    __nv_bfloat16* lo = isW ? g_wl[which] : g_xl[which];
    float4 v = reinterpret_cast<const float4*>(src)[i];
    uint2 H, L;
    f4_to_hilo(v, H, L);
    reinterpret_cast<uint2*>(hi)[i] = H;
    reinterpret_cast<uint2*>(lo)[i] = L;
}

__global__ __launch_bounds__(256)
void er_split_kernel(const float* __restrict__ Er, int n4) {
    int i = blockIdx.x * blockDim.x + threadIdx.x;
    if (i >= n4) return;
    float4 v = reinterpret_cast<const float4*>(Er)[i];
    uint2 H, L;
    f4_to_hilo(v, H, L);
    reinterpret_cast<uint2*>(g_erh)[i] = H;
    reinterpret_cast<uint2*>(g_erl)[i] = L;
}

__global__ __launch_bounds__(1024)
void zero_rowsum_kernel() {
    g_rowsum[blockIdx.x * 1024 + threadIdx.x] = 0.f;
}

// ---------------------------------------------------------------------------
// Projection GEMM on mma.sync; epilogue writes bf16 hi/lo q/k/v.
// ---------------------------------------------------------------------------
#define PROW 40

__global__ __launch_bounds__(256, 1)
void proj_mma_kernel(int which, const float* __restrict__ bias) {
    __shared__ __nv_bfloat16 sm[4][128 * PROW];   // Ah, Al, Bh, Bl

    const __nv_bfloat16* Ah = g_xh[which];
    const __nv_bfloat16* Al = g_xl[which];
    const __nv_bfloat16* Bh = g_wh[which];
    const __nv_bfloat16* Bl = g_wl[which];
    __nv_bfloat16* oh = (which == 0) ? g_qh : (which == 1) ? g_kh : g_vh;
    __nv_bfloat16* ol = (which == 0) ? g_ql : (which == 1) ? g_kl : g_vl;

    const int tid = threadIdx.x;
    const int wid = tid >> 5;
    const int lid = tid & 31;
    const int wm = wid & 1;
    const int wn = wid >> 1;
    const int m0 = blockIdx.y * 128;
    const int n0 = blockIdx.x * 128;

    const int a_row = (lid & 7) + ((lid >> 3) & 1) * 8;
    const int a_kh  = (lid >= 16) ? 8 : 0;
    const int b_n   = (lid & 7) + ((lid >= 16) ? 8 : 0);
    const int b_kh  = ((lid >> 3) & 1) * 8;

    const uint32_t sA_h = smem_u32(sm[0]);
    const uint32_t sA_l = smem_u32(sm[1]);
    const uint32_t sB_h = smem_u32(sm[2]);
    const uint32_t sB_l = smem_u32(sm[3]);

    float acc[4][4][4] = {};

    for (int c = 0; c < DM / 32; ++c) {
        const int k0g = c * 32;
        #pragma unroll
        for (int p = 0; p < 4; ++p) {
            const __nv_bfloat16* g = (p == 0) ? Ah : (p == 1) ? Al : (p == 2) ? Bh : Bl;
            const int rbase = (p < 2) ? m0 : n0;
            #pragma unroll
            for (int it = 0; it < 4; ++it) {
                int idx = tid + it * 256;
                int r = idx >> 3, seg = idx & 7;
                uint2 v = *reinterpret_cast<const uint2*>(
                    g + (size_t)(rbase + r) * DM + k0g + seg * 4);
                *reinterpret_cast<uint2*>(&sm[p][r * PROW + seg * 4]) = v;
            }
        }
        __syncthreads();

        #pragma unroll
        for (int ks = 0; ks < 2; ++ks) {
            const int k0 = ks * 16;
            uint32_t fAh[4][4], fAl[4][4], fBh[4][2], fBl[4][2];
            #pragma unroll
            for (int mi = 0; mi < 4; ++mi) {
                uint32_t off = (uint32_t)(((wm * 64 + mi * 16 + a_row) * PROW
                                           + k0 + a_kh) * 2);
                ldsm_x4(fAh[mi], sA_h + off);
                ldsm_x4(fAl[mi], sA_l + off);
            }
            #pragma unroll
            for (int pp = 0; pp < 2; ++pp) {
                uint32_t off = (uint32_t)(((wn * 32 + pp * 16 + b_n) * PROW
                                           + k0 + b_kh) * 2);
                uint32_t t[4];
                ldsm_x4(t, sB_h + off);
                fBh[pp * 2][0] = t[0]; fBh[pp * 2][1] = t[1];
                fBh[pp * 2 + 1][0] = t[2]; fBh[pp * 2 + 1][1] = t[3];
                ldsm_x4(t, sB_l + off);
                fBl[pp * 2][0] = t[0]; fBl[pp * 2][1] = t[1];
                fBl[pp * 2 + 1][0] = t[2]; fBl[pp * 2 + 1][1] = t[3];
            }
            #pragma unroll
            for (int mi = 0; mi < 4; ++mi)
                #pragma unroll
                for (int ni = 0; ni < 4; ++ni) {
                    mma_bf16(acc[mi][ni], fAh[mi], fBh[ni][0], fBh[ni][1]);
                    mma_bf16(acc[mi][ni], fAh[mi], fBl[ni][0], fBl[ni][1]);
                    mma_bf16(acc[mi][ni], fAl[mi], fBh[ni][0], fBh[ni][1]);
                }
        }
        __syncthreads();
    }

    const int rq = lid >> 2, rr = (lid & 3) * 2;
    #pragma unroll
    for (int mi = 0; mi < 4; ++mi) {
        #pragma unroll
        for (int half = 0; half < 2; ++half) {
            const int m = m0 + wm * 64 + mi * 16 + rq + half * 8;
            const int bb = m >> 10, s = m & 1023;
            #pragma unroll
            for (int ni = 0; ni < 4; ++ni) {
                const int n = n0 + wn * 32 + ni * 8 + rr;
                const int h = n >> 6, d = n & 63;
                float ox = acc[mi][ni][half * 2 + 0] + bias[n];
                float oy = acc[mi][ni][half * 2 + 1] + bias[n + 1];
                __nv_bfloat16 hx = __float2bfloat16(ox);
                __nv_bfloat16 hy = __float2bfloat16(oy);
                __nv_bfloat16 lx = __float2bfloat16(ox - __bfloat162float(hx));
                __nv_bfloat16 ly = __float2bfloat16(oy - __bfloat162float(hy));
                size_t o = ((size_t)((bb * NH + h) * SQ + s)) * HD + d;
                *reinterpret_cast<__nv_bfloat162*>(&oh[o]) = __nv_bfloat162(hx, hy);
                *reinterpret_cast<__nv_bfloat162*>(&ol[o]) = __nv_bfloat162(lx, ly);
            }
        }
    }
}

// ---------------------------------------------------------------------------
// Logits + exp + rowsum: 128x128 tile per block.
// attn[b,h,i,j] = exp((q.k + q.Er[1023+j-i]) / 8); rowsum accumulated atomically.
// ---------------------------------------------------------------------------
#define LROW 72
#define ES_STRIDE 258
#define L_SMEM (4 * 128 * LROW * 2 + 128 * ES_STRIDE * 4)   // 205824 B

__global__ __launch_bounds__(256, 1)
void logits_mma_kernel(float* __restrict__ attn) {
    extern __shared__ char lsm[];
    __nv_bfloat16* Qh = reinterpret_cast<__nv_bfloat16*>(lsm);
    __nv_bfloat16* Ql = Qh + 128 * LROW;
    __nv_bfloat16* Bh = Ql + 128 * LROW;
    __nv_bfloat16* Bl = Bh + 128 * LROW;
    float* Es = reinterpret_cast<float*>(lsm + 4 * 128 * LROW * 2);

    const int bh = blockIdx.z;
    const int h  = bh & 15;
    const int i0 = blockIdx.y * 128;
    const int j0 = blockIdx.x * 128;
    const int l0b = 896 + j0 - i0;           // Er row for t=0; l0b+255 <= 2047 < ER_L

    const __nv_bfloat16* qh = g_qh + (size_t)bh * SQ * HD;
    const __nv_bfloat16* ql = g_ql + (size_t)bh * SQ * HD;
    const __nv_bfloat16* kh = g_kh + (size_t)bh * SQ * HD;
    const __nv_bfloat16* kl = g_kl + (size_t)bh * SQ * HD;
    const __nv_bfloat16* eh = g_erh + (size_t)h * ER_L * HD;
    const __nv_bfloat16* el = g_erl + (size_t)h * ER_L * HD;

    const int tid = threadIdx.x;
    const int wid = tid >> 5;
    const int lid = tid & 31;
    const int wm = wid & 3;
    const int wn = wid >> 2;

    const int a_row = (lid & 7) + ((lid >> 3) & 1) * 8;
    const int a_kh  = (lid >= 16) ? 8 : 0;
    const int b_n   = (lid & 7) + ((lid >= 16) ? 8 : 0);
    const int b_kh  = ((lid >> 3) & 1) * 8;
    const int rq = lid >> 2, rr = (lid & 3) * 2;

    const uint32_t sQh = smem_u32(Qh), sQl = smem_u32(Ql);
    const uint32_t sBh = smem_u32(Bh), sBl = smem_u32(Bl);

    // Q tile copy (bf16 direct)
    #pragma unroll
    for (int it = 0; it < 8; ++it) {
        int idx = tid + it * 256;
        int r = idx >> 4, c4 = idx & 15;
        size_t off = (size_t)(i0 + r) * HD + c4 * 4;
        *reinterpret_cast<uint2*>(&Qh[r * LROW + c4 * 4]) =
            *reinterpret_cast<const uint2*>(&qh[off]);
        *reinterpret_cast<uint2*>(&Ql[r * LROW + c4 * 4]) =
            *reinterpret_cast<const uint2*>(&ql[off]);
    }

    float acc[2][8][4];

    #pragma unroll
    for (int phase = 0; phase < 3; ++phase) {
        __syncthreads();
        // B tile copy
        #pragma unroll
        for (int it = 0; it < 8; ++it) {
            int idx = tid + it * 256;
            int r = idx >> 4, c4 = idx & 15;
            const __nv_bfloat16 *srcH, *srcL;
            size_t off;
            if (phase < 2) {
                off = (size_t)(l0b + phase * 128 + r) * HD + c4 * 4;
                srcH = eh; srcL = el;
            } else {
                off = (size_t)(j0 + r) * HD + c4 * 4;
                srcH = kh; srcL = kl;
            }
            *reinterpret_cast<uint2*>(&Bh[r * LROW + c4 * 4]) =
                *reinterpret_cast<const uint2*>(&srcH[off]);
            *reinterpret_cast<uint2*>(&Bl[r * LROW + c4 * 4]) =
                *reinterpret_cast<const uint2*>(&srcL[off]);
        }
        __syncthreads();

        #pragma unroll
        for (int mi = 0; mi < 2; ++mi)
            #pragma unroll
            for (int ni = 0; ni < 8; ++ni)
                #pragma unroll
                for (int e = 0; e < 4; ++e) acc[mi][ni][e] = 0.f;

        #pragma unroll
        for (int ks = 0; ks < 4; ++ks) {
            const int k0 = ks * 16;
            uint32_t fAh[2][4], fAl[2][4], fBh[8][2], fBl[8][2];
            #pragma unroll
            for (int mi = 0; mi < 2; ++mi) {
                uint32_t off = (uint32_t)(((wm * 32 + mi * 16 + a_row) * LROW
                                           + k0 + a_kh) * 2);
                ldsm_x4(fAh[mi], sQh + off);
                ldsm_x4(fAl[mi], sQl + off);
            }
            #pragma unroll
            for (int pp = 0; pp < 4; ++pp) {
                uint32_t off = (uint32_t)(((wn * 64 + pp * 16 + b_n) * LROW
                                           + k0 + b_kh) * 2);
                uint32_t t4[4];
                ldsm_x4(t4, sBh + off);
                fBh[pp * 2][0] = t4[0]; fBh[pp * 2][1] = t4[1];
                fBh[pp * 2 + 1][0] = t4[2]; fBh[pp * 2 + 1][1] = t4[3];
                ldsm_x4(t4, sBl + off);
                fBl[pp * 2][0] = t4[0]; fBl[pp * 2][1] = t4[1];
                fBl[pp * 2 + 1][0] = t4[2]; fBl[pp * 2 + 1][1] = t4[3];
            }
            #pragma unroll
            for (int mi = 0; mi < 2; ++mi)
                #pragma unroll
                for (int ni = 0; ni < 8; ++ni) {
                    mma_bf16(acc[mi][ni], fAh[mi], fBh[ni][0], fBh[ni][1]);
                    mma_bf16(acc[mi][ni], fAh[mi], fBl[ni][0], fBl[ni][1]);
                    mma_bf16(acc[mi][ni], fAl[mi], fBh[ni][0], fBh[ni][1]);
                }
        }

        if (phase < 2) {
            #pragma unroll
            for (int mi = 0; mi < 2; ++mi)
                #pragma unroll
                for (int half = 0; half < 2; ++half) {
                    const int row = wm * 32 + mi * 16 + rq + half * 8;
                    #pragma unroll
                    for (int ni = 0; ni < 8; ++ni) {
                        const int col = phase * 128 + wn * 64 + ni * 8 + rr;
                        *reinterpret_cast<float2*>(&Es[row * ES_STRIDE + col]) =
                            make_float2(acc[mi][ni][half * 2], acc[mi][ni][half * 2 + 1]);
                    }
                }
        }
    }

    __syncthreads();   // all Es writes visible

    // epilogue: exp + attn store + row-sum accumulation
    #pragma unroll
    for (int mi = 0; mi < 2; ++mi)
        #pragma unroll
        for (int half = 0; half < 2; ++half) {
            const int ip = wm * 32 + mi * 16 + rq + half * 8;
            const float* EsRow = Es + (size_t)ip * ES_STRIDE + (127 - ip);
            float* arow = attn + ((size_t)bh * SQ + i0 + ip) * SQ + j0;
            float rs = 0.f;
            #pragma unroll
            for (int ni = 0; ni < 8; ++ni) {
                const int jp = wn * 64 + ni * 8 + rr;
                float ex = __expf((acc[mi][ni][half * 2 + 0] + EsRow[jp])     * 0.125f);
                float ey = __expf((acc[mi][ni][half * 2 + 1] + EsRow[jp + 1]) * 0.125f);
                *reinterpret_cast<float2*>(&arow[jp]) = make_float2(ex, ey);
                rs += ex + ey;
            }
            rs += __shfl_xor_sync(0xffffffffu, rs, 1);
            rs += __shfl_xor_sync(0xffffffffu, rs, 2);
            if ((lid & 3) == 0)
                atomicAdd(&g_rowsum[(size_t)bh * SQ + i0 + ip], rs);
        }
}

// ---------------------------------------------------------------------------
// av + softmax normalization: reads exp values, normalizes in place,
// out = P_norm . v.  Block: 128 rows x 64 cols per (b,h).
// ---------------------------------------------------------------------------
#define VROW 72

__global__ __launch_bounds__(256, 2)
void av_mma_kernel(float* __restrict__ attn, float* __restrict__ out) {
    __shared__ __nv_bfloat16 Ph[128 * VROW], Pl[128 * VROW];
    __shared__ __nv_bfloat16 Vh[64 * VROW],  Vl[64 * VROW];
    __shared__ float s_inv[128];

    const int bh = blockIdx.y;
    const int b = bh >> 4, h = bh & 15;
    const int i0 = blockIdx.x * 128;
    float* ab = attn + (size_t)bh * SQ * SQ;
    const __nv_bfloat16* vh = g_vh + (size_t)bh * SQ * HD;
    const __nv_bfloat16* vl = g_vl + (size_t)bh * SQ * HD;

    const int tid = threadIdx.x;
    const int wid = tid >> 5;
    const int lid = tid & 31;
    const int wm = wid & 3;
    const int wn = wid >> 2;

    const int a_row = (lid & 7) + ((lid >> 3) & 1) * 8;
    const int a_kh  = (lid >= 16) ? 8 : 0;
    const int b_n   = (lid & 7) + ((lid >= 16) ? 8 : 0);
    const int b_kh  = ((lid >> 3) & 1) * 8;
    const int rq = lid >> 2, rr = (lid & 3) * 2;

    const uint32_t sPh = smem_u32(Ph), sPl = smem_u32(Pl);
    const uint32_t sVh = smem_u32(Vh), sVl = smem_u32(Vl);

    if (tid < 128)
        s_inv[tid] = 1.0f / g_rowsum[(size_t)bh * SQ + i0 + tid];

    float acc[2][4][4] = {};

    for (int c = 0; c < SQ / 64; ++c) {
        __syncthreads();
        // P tile: load exp values, normalize, write back, convert hi/lo
        #pragma unroll
        for (int it = 0; it < 8; ++it) {
            int idx = tid + it * 256;
            int r = idx >> 4, c4 = idx & 15;
            float* ap = ab + (size_t)(i0 + r) * SQ + c * 64 + c4 * 4;
            float4 v = *reinterpret_cast<const float4*>(ap);
            const float inv = s_inv[r];
            v.x *= inv; v.y *= inv; v.z *= inv; v.w *= inv;
            *reinterpret_cast<float4*>(ap) = v;
            uint2 H, L;
            f4_to_hilo(v, H, L);
            *reinterpret_cast<uint2*>(&Ph[r * VROW + c4 * 4]) = H;
            *reinterpret_cast<uint2*>(&Pl[r * VROW + c4 * 4]) = L;
        }
        // V tile transposed from bf16 hi/lo: smem[d][j]
        #pragma unroll
        for (int it = 0; it < 4; ++it) {
            int idx = tid + it * 256;
            int j = idx >> 4, c4 = idx & 15;
            int d0 = c4 * 4;
            size_t off = (size_t)(c * 64 + j) * HD + d0;
            union { uint2 u; __nv_bfloat16 b[4]; } hv, lv;
            hv.u = *reinterpret_cast<const uint2*>(&vh[off]);
            lv.u = *reinterpret_cast<const uint2*>(&vl[off]);
            #pragma unroll
            for (int x = 0; x < 4; ++x) {
                Vh[(d0 + x) * VROW + j] = hv.b[x];
                Vl[(d0 + x) * VROW + j] = lv.b[x];
            }
        }
        __syncthreads();

        #pragma unroll
        for (int ks = 0; ks < 4; ++ks) {
            const int k0 = ks * 16;
            uint32_t fAh[2][4], fAl[2][4], fBh[4][2], fBl[4][2];
            #pragma unroll
            for (int mi = 0; mi < 2; ++mi) {
                uint32_t off = (uint32_t)(((wm * 32 + mi * 16 + a_row) * VROW
                                           + k0 + a_kh) * 2);
                ldsm_x4(fAh[mi], sPh + off);
                ldsm_x4(fAl[mi], sPl + off);
            }
            #pragma unroll
            for (int pp = 0; pp < 2; ++pp) {
                uint32_t off = (uint32_t)(((wn * 32 + pp * 16 + b_n) * VROW
                                           + k0 + b_kh) * 2);
                uint32_t t4[4];
                ldsm_x4(t4, sVh + off);
                fBh[pp * 2][0] = t4[0]; fBh[pp * 2][1] = t4[1];
                fBh[pp * 2 + 1][0] = t4[2]; fBh[pp * 2 + 1][1] = t4[3];
                ldsm_x4(t4, sVl + off);
                fBl[pp * 2][0] = t4[0]; fBl[pp * 2][1] = t4[1];
                fBl[pp * 2 + 1][0] = t4[2]; fBl[pp * 2 + 1][1] = t4[3];
            }
            #pragma unroll
            for (int mi = 0; mi < 2; ++mi)
                #pragma unroll
                for (int ni = 0; ni < 4; ++ni) {
                    mma_bf16(acc[mi][ni], fAh[mi], fBh[ni][0], fBh[ni][1]);
                    mma_bf16(acc[mi][ni], fAh[mi], fBl[ni][0], fBl[ni][1]);
                    mma_bf16(acc[mi][ni], fAl[mi], fBh[ni][0], fBh[ni][1]);
                }
        }
    }

    #pragma unroll
    for (int mi = 0; mi < 2; ++mi)
        #pragma unroll
        for (int half = 0; half < 2; ++half) {
            const int s = i0 + wm * 32 + mi * 16 + rq + half * 8;
            #pragma unroll
            for (int ni = 0; ni < 4; ++ni) {
                const int d = wn * 32 + ni * 8 + rr;
                float2 o;
                o.x = acc[mi][ni][half * 2 + 0];
                o.y = acc[mi][ni][half * 2 + 1];
                *reinterpret_cast<float2*>(
                    &out[((size_t)(b * SQ + s)) * DM + h * HD + d]) = o;
            }
        }
}

// ---------------------------------------------------------------------------
extern "C" void kernel_launch(void* const* d_in, const int* in_sizes, int n_in,
                              void* d_out, int out_size) {
    const float* query = (const float*)d_in[0];
    const float* key   = (const float*)d_in[1];
    const float* value = (const float*)d_in[2];
    const float* Wq    = (const float*)d_in[3];
    const float* bq    = (const float*)d_in[4];
    const float* Wk    = (const float*)d_in[5];
    const float* bk    = (const float*)d_in[6];
    const float* Wv    = (const float*)d_in[7];
    const float* bv    = (const float*)d_in[8];
    const float* Er    = (const float*)d_in[9];

    float* out  = (float*)d_out;                       // (4,1024,1024)
    float* attn = out + (size_t)NB * SQ * DM;          // (4,16,1024,1024)

    cudaFuncSetAttribute(logits_mma_kernel,
                         cudaFuncAttributeMaxDynamicSharedMemorySize, L_SMEM);

    const int xn4 = NB * SQ * DM / 4;
    const int wn4 = DM * DM / 4;
    const int en4 = NH * ER_L * HD / 4;                // 524544
    split_kernel<<<xn4 / 256, 256>>>(query, 0, 0, xn4);
    split_kernel<<<xn4 / 256, 256>>>(key,   1, 0, xn4);
    split_kernel<<<xn4 / 256, 256>>>(value, 2, 0, xn4);
    split_kernel<<<wn4 / 256, 256>>>(Wq, 0, 1, wn4);
    split_kernel<<<wn4 / 256, 256>>>(Wk, 1, 1, wn4);
    split_kernel<<<wn4 / 256, 256>>>(Wv, 2, 1, wn4);
    er_split_kernel<<<(en4 + 255) / 256, 256>>>(Er, en4);
    zero_rowsum_kernel<<<BH, 1024>>>();

    dim3 pg(DM / 128, NB * SQ / 128);
    proj_mma_kernel<<<pg, 256>>>(0, bq);
    proj_mma_kernel<<<pg, 256>>>(1, bk);
    proj_mma_kernel<<<pg, 256>>>(2, bv);

    dim3 lg(SQ / 128, SQ / 128, BH);                   // (8, 8, 64)
    logits_mma_kernel<<<lg, 256, L_SMEM>>>(attn);

    dim3 ag(SQ / 128, BH);                             // (8, 64)
    av_mma_kernel<<<ag, 256>>>(attn, out);
}

// round 13
// speedup vs baseline: 2.3558x; 1.1246x over previous
#include <cuda_runtime.h>
#include <cuda_bf16.h>
#include <math.h>
#include <cstdint>

#define SQ   1024
#define DM   1024
#define NH   16
#define HD   64
#define NB   4
#define BH   (NB*NH)
#define ER_L 2049

// ---------------------------------------------------------------------------
// Device scratch: projected q,k,v stored directly as bf16 hi/lo pairs.
// ---------------------------------------------------------------------------
__device__ __nv_bfloat16 g_qh[(size_t)BH * SQ * HD], g_ql[(size_t)BH * SQ * HD];
__device__ __nv_bfloat16 g_kh[(size_t)BH * SQ * HD], g_kl[(size_t)BH * SQ * HD];
__device__ __nv_bfloat16 g_vh[(size_t)BH * SQ * HD], g_vl[(size_t)BH * SQ * HD];

__device__ __nv_bfloat16 g_xh[3][(size_t)NB * SQ * DM];   // inputs hi
__device__ __nv_bfloat16 g_xl[3][(size_t)NB * SQ * DM];   // inputs lo
__device__ __nv_bfloat16 g_wh[3][(size_t)DM * DM];        // weights hi
__device__ __nv_bfloat16 g_wl[3][(size_t)DM * DM];        // weights lo

__device__ __nv_bfloat16 g_erh[(size_t)NH * ER_L * HD];   // Er hi
__device__ __nv_bfloat16 g_erl[(size_t)NH * ER_L * HD];   // Er lo

__device__ float g_rowsum[(size_t)BH * SQ];               // softmax denominators

// ---------------------------------------------------------------------------
// mma.sync + cp.async helpers
// ---------------------------------------------------------------------------
__device__ __forceinline__ uint32_t smem_u32(const void* p) {
    uint32_t a;
    asm("{ .reg .u64 t; cvta.to.shared.u64 t, %1; cvt.u32.u64 %0, t; }"
        : "=r"(a) : "l"(p));
    return a;
}
__device__ __forceinline__ void ldsm_x4(uint32_t (&r)[4], uint32_t addr) {
    asm volatile("ldmatrix.sync.aligned.m8n8.x4.shared.b16 {%0,%1,%2,%3}, [%4];"
                 : "=r"(r[0]), "=r"(r[1]), "=r"(r[2]), "=r"(r[3]) : "r"(addr));
}
__device__ __forceinline__ void mma_bf16(float (&c)[4], const uint32_t (&a)[4],
                                         const uint32_t b0, const uint32_t b1) {
    asm volatile("mma.sync.aligned.m16n8k16.row.col.f32.bf16.bf16.f32 "
                 "{%0,%1,%2,%3}, {%4,%5,%6,%7}, {%8,%9}, {%0,%1,%2,%3};"
                 : "+f"(c[0]), "+f"(c[1]), "+f"(c[2]), "+f"(c[3])
                 : "r"(a[0]), "r"(a[1]), "r"(a[2]), "r"(a[3]), "r"(b0), "r"(b1));
}
#define CP_ASYNC16(smem, gptr) \
    asm volatile("cp.async.cg.shared.global [%0], [%1], 16;" \
                 :: "r"(smem), "l"(gptr) : "memory")
#define CP_COMMIT() asm volatile("cp.async.commit_group;" ::: "memory")
#define CP_WAIT(n)  asm volatile("cp.async.wait_group %0;" :: "n"(n) : "memory")

__device__ __forceinline__ void f4_to_hilo(float4 v, uint2& H, uint2& L) {
    union { __nv_bfloat16 b[4]; uint2 u; } hh, ll;
    hh.b[0] = __float2bfloat16(v.x);
    hh.b[1] = __float2bfloat16(v.y);
    hh.b[2] = __float2bfloat16(v.z);
    hh.b[3] = __float2bfloat16(v.w);
    ll.b[0] = __float2bfloat16(v.x - __bfloat162float(hh.b[0]));
    ll.b[1] = __float2bfloat16(v.y - __bfloat162float(hh.b[1]));
    ll.b[2] = __float2bfloat16(v.z - __bfloat162float(hh.b[2]));
    ll.b[3] = __float2bfloat16(v.w - __bfloat162float(hh.b[3]));
    H = hh.u; L = ll.u;
}

// ---------------------------------------------------------------------------
// fp32 -> bf16 hi/lo splits
// ---------------------------------------------------------------------------
__global__ __launch_bounds__(256)
void split_kernel(const float* __restrict__ src, int which, int isW, int n4) {
    int i = blockIdx.x * blockDim.x + threadIdx.x;
    if (i >= n4) return;
    __nv_bfloat16* hi = isW ? g_wh[which] : g_xh[which];
    __nv_bfloat16* lo = isW ? g_wl[which] : g_xl[which];
    float4 v = reinterpret_cast<const float4*>(src)[i];
    uint2 H, L;
    f4_to_hilo(v, H, L);
    reinterpret_cast<uint2*>(hi)[i] = H;
    reinterpret_cast<uint2*>(lo)[i] = L;
}

__global__ __launch_bounds__(256)
void er_split_kernel(const float* __restrict__ Er, int n4) {
    int i = blockIdx.x * blockDim.x + threadIdx.x;
    if (i >= n4) return;
    float4 v = reinterpret_cast<const float4*>(Er)[i];
    uint2 H, L;
    f4_to_hilo(v, H, L);
    reinterpret_cast<uint2*>(g_erh)[i] = H;
    reinterpret_cast<uint2*>(g_erl)[i] = L;
}

__global__ __launch_bounds__(1024)
void zero_rowsum_kernel() {
    g_rowsum[blockIdx.x * 1024 + threadIdx.x] = 0.f;
}

// ---------------------------------------------------------------------------
// Projection GEMM on mma.sync; cp.async double-buffered; epilogue writes
// bf16 hi/lo q/k/v.
// ---------------------------------------------------------------------------
#define PROW 40
#define P_PLANE (128 * PROW)              // bf16 elements per plane
#define P_SMEM  (2 * 4 * P_PLANE * 2)     // 81920 bytes

__global__ __launch_bounds__(256, 1)
void proj_mma_kernel(int which, const float* __restrict__ bias) {
    extern __shared__ __nv_bfloat16 psm[];   // [2][4][128*PROW]

    const __nv_bfloat16* Ah = g_xh[which];
    const __nv_bfloat16* Al = g_xl[which];
    const __nv_bfloat16* Bh = g_wh[which];
    const __nv_bfloat16* Bl = g_wl[which];
    __nv_bfloat16* oh = (which == 0) ? g_qh : (which == 1) ? g_kh : g_vh;
    __nv_bfloat16* ol = (which == 0) ? g_ql : (which == 1) ? g_kl : g_vl;

    const int tid = threadIdx.x;
    const int wid = tid >> 5;
    const int lid = tid & 31;
    const int wm = wid & 1;
    const int wn = wid >> 1;
    const int m0 = blockIdx.y * 128;
    const int n0 = blockIdx.x * 128;

    const int a_row = (lid & 7) + ((lid >> 3) & 1) * 8;
    const int a_kh  = (lid >= 16) ? 8 : 0;
    const int b_n   = (lid & 7) + ((lid >= 16) ? 8 : 0);
    const int b_kh  = ((lid >> 3) & 1) * 8;

    const uint32_t sbase = smem_u32(psm);

    float acc[4][4][4] = {};

    auto load_chunk = [&](int c, int buf) {
        const int k0g = c * 32;
        #pragma unroll
        for (int p = 0; p < 4; ++p) {
            const __nv_bfloat16* g = (p == 0) ? Ah : (p == 1) ? Al
                                    : (p == 2) ? Bh : Bl;
            const int rbase = (p < 2) ? m0 : n0;
            #pragma unroll
            for (int it = 0; it < 2; ++it) {
                int idx = tid + it * 256;        // 0..511
                int r = idx >> 2, seg = idx & 3; // seg: 8 bf16 = 16 B
                uint32_t dst = sbase +
                    (uint32_t)(((buf * 4 + p) * P_PLANE + r * PROW + seg * 8) * 2);
                CP_ASYNC16(dst, g + (size_t)(rbase + r) * DM + k0g + seg * 8);
            }
        }
        CP_COMMIT();
    };

    load_chunk(0, 0);

    const int NCH = DM / 32;
    for (int c = 0; c < NCH; ++c) {
        const int buf = c & 1;
        if (c + 1 < NCH) { load_chunk(c + 1, (c + 1) & 1); CP_WAIT(1); }
        else             { CP_WAIT(0); }
        __syncthreads();

        const uint32_t sA_h = sbase + (uint32_t)((buf * 4 + 0) * P_PLANE * 2);
        const uint32_t sA_l = sbase + (uint32_t)((buf * 4 + 1) * P_PLANE * 2);
        const uint32_t sB_h = sbase + (uint32_t)((buf * 4 + 2) * P_PLANE * 2);
        const uint32_t sB_l = sbase + (uint32_t)((buf * 4 + 3) * P_PLANE * 2);

        #pragma unroll
        for (int ks = 0; ks < 2; ++ks) {
            const int k0 = ks * 16;
            uint32_t fAh[4][4], fAl[4][4], fBh[4][2], fBl[4][2];
            #pragma unroll
            for (int mi = 0; mi < 4; ++mi) {
                uint32_t off = (uint32_t)(((wm * 64 + mi * 16 + a_row) * PROW
                                           + k0 + a_kh) * 2);
                ldsm_x4(fAh[mi], sA_h + off);
                ldsm_x4(fAl[mi], sA_l + off);
            }
            #pragma unroll
            for (int pp = 0; pp < 2; ++pp) {
                uint32_t off = (uint32_t)(((wn * 32 + pp * 16 + b_n) * PROW
                                           + k0 + b_kh) * 2);
                uint32_t t[4];
                ldsm_x4(t, sB_h + off);
                fBh[pp * 2][0] = t[0]; fBh[pp * 2][1] = t[1];
                fBh[pp * 2 + 1][0] = t[2]; fBh[pp * 2 + 1][1] = t[3];
                ldsm_x4(t, sB_l + off);
                fBl[pp * 2][0] = t[0]; fBl[pp * 2][1] = t[1];
                fBl[pp * 2 + 1][0] = t[2]; fBl[pp * 2 + 1][1] = t[3];
            }
            #pragma unroll
            for (int mi = 0; mi < 4; ++mi)
                #pragma unroll
                for (int ni = 0; ni < 4; ++ni) {
                    mma_bf16(acc[mi][ni], fAh[mi], fBh[ni][0], fBh[ni][1]);
                    mma_bf16(acc[mi][ni], fAh[mi], fBl[ni][0], fBl[ni][1]);
                    mma_bf16(acc[mi][ni], fAl[mi], fBh[ni][0], fBh[ni][1]);
                }
        }
        __syncthreads();
    }

    const int rq = lid >> 2, rr = (lid & 3) * 2;
    #pragma unroll
    for (int mi = 0; mi < 4; ++mi) {
        #pragma unroll
        for (int half = 0; half < 2; ++half) {
            const int m = m0 + wm * 64 + mi * 16 + rq + half * 8;
            const int bb = m >> 10, s = m & 1023;
            #pragma unroll
            for (int ni = 0; ni < 4; ++ni) {
                const int n = n0 + wn * 32 + ni * 8 + rr;
                const int h = n >> 6, d = n & 63;
                float ox = acc[mi][ni][half * 2 + 0] + bias[n];
                float oy = acc[mi][ni][half * 2 + 1] + bias[n + 1];
                __nv_bfloat16 hx = __float2bfloat16(ox);
                __nv_bfloat16 hy = __float2bfloat16(oy);
                __nv_bfloat16 lx = __float2bfloat16(ox - __bfloat162float(hx));
                __nv_bfloat16 ly = __float2bfloat16(oy - __bfloat162float(hy));
                size_t o = ((size_t)((bb * NH + h) * SQ + s)) * HD + d;
                *reinterpret_cast<__nv_bfloat162*>(&oh[o]) = __nv_bfloat162(hx, hy);
                *reinterpret_cast<__nv_bfloat162*>(&ol[o]) = __nv_bfloat162(lx, ly);
            }
        }
    }
}

// ---------------------------------------------------------------------------
// Logits + exp + rowsum: 128x128 tile per block.
// Q fragments cached in registers; B tiles (Er0, Er1, K) pipelined through
// two cp.async ping-pong buffers.
// attn[b,h,i,j] = exp((q.k + q.Er[1023+j-i]) / 8); rowsum via atomicAdd.
// ---------------------------------------------------------------------------
#define LROW 72
#define L_PLANE (128 * LROW)                 // bf16 per plane
#define L_BUF   (2 * L_PLANE)                // 2 planes (hi+lo)
#define ES_STRIDE 258
#define L_SMEM (2 * L_BUF * 2 + 128 * ES_STRIDE * 4)   // 73728 + 132096 = 205824

__global__ __launch_bounds__(256, 1)
void logits_mma_kernel(float* __restrict__ attn) {
    extern __shared__ char lsm[];
    __nv_bfloat16* Bbuf = reinterpret_cast<__nv_bfloat16*>(lsm);
    float* Es = reinterpret_cast<float*>(lsm + 2 * L_BUF * 2);

    const int bh = blockIdx.z;
    const int h  = bh & 15;
    const int i0 = blockIdx.y * 128;
    const int j0 = blockIdx.x * 128;
    const int l0b = 896 + j0 - i0;           // Er row for t=0; l0b+255 <= 2047

    const __nv_bfloat16* qh = g_qh + (size_t)bh * SQ * HD;
    const __nv_bfloat16* ql = g_ql + (size_t)bh * SQ * HD;
    const __nv_bfloat16* kh = g_kh + (size_t)bh * SQ * HD;
    const __nv_bfloat16* kl = g_kl + (size_t)bh * SQ * HD;
    const __nv_bfloat16* eh = g_erh + (size_t)h * ER_L * HD;
    const __nv_bfloat16* el = g_erl + (size_t)h * ER_L * HD;

    const int tid = threadIdx.x;
    const int wid = tid >> 5;
    const int lid = tid & 31;
    const int wm = wid & 3;
    const int wn = wid >> 2;

    const int a_row = (lid & 7) + ((lid >> 3) & 1) * 8;
    const int a_kh  = (lid >= 16) ? 8 : 0;
    const int b_n   = (lid & 7) + ((lid >= 16) ? 8 : 0);
    const int b_kh  = ((lid >> 3) & 1) * 8;
    const int rq = lid >> 2, rr = (lid & 3) * 2;

    const uint32_t sb = smem_u32(Bbuf);

    // cp.async loader: 2 planes (hi/lo) of 128 rows x 64 bf16 into buffer `buf`
    auto load_tile = [&](const __nv_bfloat16* pH, const __nv_bfloat16* pL,
                         size_t row0, int buf) {
        #pragma unroll
        for (int it = 0; it < 4; ++it) {
            int idx = tid + it * 256;            // 0..1023
            int r = idx >> 3, seg = idx & 7;     // seg: 8 bf16 = 16 B
            size_t goff = (row0 + r) * HD + seg * 8;
            uint32_t d0 = sb + (uint32_t)((buf * L_BUF + r * LROW + seg * 8) * 2);
            CP_ASYNC16(d0, pH + goff);
            CP_ASYNC16(d0 + (uint32_t)(L_PLANE * 2), pL + goff);
        }
        CP_COMMIT();
    };

    // ---- Q into buf0, then hoist Q fragments to registers ----
    load_tile(qh, ql, (size_t)i0, 0);
    CP_WAIT(0);
    __syncthreads();

    uint32_t fQh[4][2][4], fQl[4][2][4];
    #pragma unroll
    for (int ks = 0; ks < 4; ++ks)
        #pragma unroll
        for (int mi = 0; mi < 2; ++mi) {
            uint32_t off = (uint32_t)(((wm * 32 + mi * 16 + a_row) * LROW
                                       + ks * 16 + a_kh) * 2);
            ldsm_x4(fQh[ks][mi], sb + off);
            ldsm_x4(fQl[ks][mi], sb + (uint32_t)(L_PLANE * 2) + off);
        }
    __syncthreads();   // everyone done reading buf0

    // prologue: Er chunk0 -> buf0, Er chunk1 -> buf1
    load_tile(eh, el, (size_t)l0b, 0);
    load_tile(eh, el, (size_t)(l0b + 128), 1);

    float acc[2][8][4];

    #pragma unroll
    for (int phase = 0; phase < 3; ++phase) {
        if (phase < 2) CP_WAIT(1); else CP_WAIT(0);
        __syncthreads();

        const int buf = (phase == 1) ? 1 : 0;
        const uint32_t bH = sb + (uint32_t)(buf * L_BUF * 2);
        const uint32_t bL = bH + (uint32_t)(L_PLANE * 2);

        #pragma unroll
        for (int mi = 0; mi < 2; ++mi)
            #pragma unroll
            for (int ni = 0; ni < 8; ++ni)
                #pragma unroll
                for (int e = 0; e < 4; ++e) acc[mi][ni][e] = 0.f;

        #pragma unroll
        for (int ks = 0; ks < 4; ++ks) {
            const int k0 = ks * 16;
            uint32_t fBh[8][2], fBl[8][2];
            #pragma unroll
            for (int pp = 0; pp < 4; ++pp) {
                uint32_t off = (uint32_t)(((wn * 64 + pp * 16 + b_n) * LROW
                                           + k0 + b_kh) * 2);
                uint32_t t4[4];
                ldsm_x4(t4, bH + off);
                fBh[pp * 2][0] = t4[0]; fBh[pp * 2][1] = t4[1];
                fBh[pp * 2 + 1][0] = t4[2]; fBh[pp * 2 + 1][1] = t4[3];
                ldsm_x4(t4, bL + off);
                fBl[pp * 2][0] = t4[0]; fBl[pp * 2][1] = t4[1];
                fBl[pp * 2 + 1][0] = t4[2]; fBl[pp * 2 + 1][1] = t4[3];
            }
            #pragma unroll
            for (int mi = 0; mi < 2; ++mi)
                #pragma unroll
                for (int ni = 0; ni < 8; ++ni) {
                    mma_bf16(acc[mi][ni], fQh[ks][mi], fBh[ni][0], fBh[ni][1]);
                    mma_bf16(acc[mi][ni], fQh[ks][mi], fBl[ni][0], fBl[ni][1]);
                    mma_bf16(acc[mi][ni], fQl[ks][mi], fBh[ni][0], fBh[ni][1]);
                }
        }

        if (phase == 0) {
            __syncthreads();                     // all reads of buf0 done
            load_tile(kh, kl, (size_t)j0, 0);    // K -> buf0 (flies under phase1)
        }

        if (phase < 2) {
            #pragma unroll
            for (int mi = 0; mi < 2; ++mi)
                #pragma unroll
                for (int half = 0; half < 2; ++half) {
                    const int row = wm * 32 + mi * 16 + rq + half * 8;
                    #pragma unroll
                    for (int ni = 0; ni < 8; ++ni) {
                        const int col = phase * 128 + wn * 64 + ni * 8 + rr;
                        *reinterpret_cast<float2*>(&Es[row * ES_STRIDE + col]) =
                            make_float2(acc[mi][ni][half * 2], acc[mi][ni][half * 2 + 1]);
                    }
                }
        }
    }

    __syncthreads();   // all Es writes visible

    // epilogue: exp + attn store + row-sum accumulation
    #pragma unroll
    for (int mi = 0; mi < 2; ++mi)
        #pragma unroll
        for (int half = 0; half < 2; ++half) {
            const int ip = wm * 32 + mi * 16 + rq + half * 8;
            const float* EsRow = Es + (size_t)ip * ES_STRIDE + (127 - ip);
            float* arow = attn + ((size_t)bh * SQ + i0 + ip) * SQ + j0;
            float rs = 0.f;
            #pragma unroll
            for (int ni = 0; ni < 8; ++ni) {
                const int jp = wn * 64 + ni * 8 + rr;
                float ex = __expf((acc[mi][ni][half * 2 + 0] + EsRow[jp])     * 0.125f);
                float ey = __expf((acc[mi][ni][half * 2 + 1] + EsRow[jp + 1]) * 0.125f);
                *reinterpret_cast<float2*>(&arow[jp]) = make_float2(ex, ey);
                rs += ex + ey;
            }
            rs += __shfl_xor_sync(0xffffffffu, rs, 1);
            rs += __shfl_xor_sync(0xffffffffu, rs, 2);
            if ((lid & 3) == 0)
                atomicAdd(&g_rowsum[(size_t)bh * SQ + i0 + ip], rs);
        }
}

// ---------------------------------------------------------------------------
// av + softmax normalization: reads exp values, normalizes in place,
// out = P_norm . v.  Block: 128 rows x 64 cols per (b,h).
// ---------------------------------------------------------------------------
#define VROW 72

__global__ __launch_bounds__(256, 2)
void av_mma_kernel(float* __restrict__ attn, float* __restrict__ out) {
    __shared__ __nv_bfloat16 Ph[128 * VROW], Pl[128 * VROW];
    __shared__ __nv_bfloat16 Vh[64 * VROW],  Vl[64 * VROW];
    __shared__ float s_inv[128];

    const int bh = blockIdx.y;
    const int b = bh >> 4, h = bh & 15;
    const int i0 = blockIdx.x * 128;
    float* ab = attn + (size_t)bh * SQ * SQ;
    const __nv_bfloat16* vh = g_vh + (size_t)bh * SQ * HD;
    const __nv_bfloat16* vl = g_vl + (size_t)bh * SQ * HD;

    const int tid = threadIdx.x;
    const int wid = tid >> 5;
    const int lid = tid & 31;
    const int wm = wid & 3;
    const int wn = wid >> 2;

    const int a_row = (lid & 7) + ((lid >> 3) & 1) * 8;
    const int a_kh  = (lid >= 16) ? 8 : 0;
    const int b_n   = (lid & 7) + ((lid >= 16) ? 8 : 0);
    const int b_kh  = ((lid >> 3) & 1) * 8;
    const int rq = lid >> 2, rr = (lid & 3) * 2;

    const uint32_t sPh = smem_u32(Ph), sPl = smem_u32(Pl);
    const uint32_t sVh = smem_u32(Vh), sVl = smem_u32(Vl);

    if (tid < 128)
        s_inv[tid] = 1.0f / g_rowsum[(size_t)bh * SQ + i0 + tid];

    float acc[2][4][4] = {};

    for (int c = 0; c < SQ / 64; ++c) {
        __syncthreads();
        // P tile: load exp values, normalize, write back, convert hi/lo
        #pragma unroll
        for (int it = 0; it < 8; ++it) {
            int idx = tid + it * 256;
            int r = idx >> 4, c4 = idx & 15;
            float* ap = ab + (size_t)(i0 + r) * SQ + c * 64 + c4 * 4;
            float4 v = *reinterpret_cast<const float4*>(ap);
            const float inv = s_inv[r];
            v.x *= inv; v.y *= inv; v.z *= inv; v.w *= inv;
            *reinterpret_cast<float4*>(ap) = v;
            uint2 H, L;
            f4_to_hilo(v, H, L);
            *reinterpret_cast<uint2*>(&Ph[r * VROW + c4 * 4]) = H;
            *reinterpret_cast<uint2*>(&Pl[r * VROW + c4 * 4]) = L;
        }
        // V tile transposed from bf16 hi/lo: smem[d][j]
        #pragma unroll
        for (int it = 0; it < 4; ++it) {
            int idx = tid + it * 256;
            int j = idx >> 4, c4 = idx & 15;
            int d0 = c4 * 4;
            size_t off = (size_t)(c * 64 + j) * HD + d0;
            union { uint2 u; __nv_bfloat16 b[4]; } hv, lv;
            hv.u = *reinterpret_cast<const uint2*>(&vh[off]);
            lv.u = *reinterpret_cast<const uint2*>(&vl[off]);
            #pragma unroll
            for (int x = 0; x < 4; ++x) {
                Vh[(d0 + x) * VROW + j] = hv.b[x];
                Vl[(d0 + x) * VROW + j] = lv.b[x];
            }
        }
        __syncthreads();

        #pragma unroll
        for (int ks = 0; ks < 4; ++ks) {
            const int k0 = ks * 16;
            uint32_t fAh[2][4], fAl[2][4], fBh[4][2], fBl[4][2];
            #pragma unroll
            for (int mi = 0; mi < 2; ++mi) {
                uint32_t off = (uint32_t)(((wm * 32 + mi * 16 + a_row) * VROW
                                           + k0 + a_kh) * 2);
                ldsm_x4(fAh[mi], sPh + off);
                ldsm_x4(fAl[mi], sPl + off);
            }
            #pragma unroll
            for (int pp = 0; pp < 2; ++pp) {
                uint32_t off = (uint32_t)(((wn * 32 + pp * 16 + b_n) * VROW
                                           + k0 + b_kh) * 2);
                uint32_t t4[4];
                ldsm_x4(t4, sVh + off);
                fBh[pp * 2][0] = t4[0]; fBh[pp * 2][1] = t4[1];
                fBh[pp * 2 + 1][0] = t4[2]; fBh[pp * 2 + 1][1] = t4[3];
                ldsm_x4(t4, sVl + off);
                fBl[pp * 2][0] = t4[0]; fBl[pp * 2][1] = t4[1];
                fBl[pp * 2 + 1][0] = t4[2]; fBl[pp * 2 + 1][1] = t4[3];
            }
            #pragma unroll
            for (int mi = 0; mi < 2; ++mi)
                #pragma unroll
                for (int ni = 0; ni < 4; ++ni) {
                    mma_bf16(acc[mi][ni], fAh[mi], fBh[ni][0], fBh[ni][1]);
                    mma_bf16(acc[mi][ni], fAh[mi], fBl[ni][0], fBl[ni][1]);
                    mma_bf16(acc[mi][ni], fAl[mi], fBh[ni][0], fBh[ni][1]);
                }
        }
    }

    #pragma unroll
    for (int mi = 0; mi < 2; ++mi)
        #pragma unroll
        for (int half = 0; half < 2; ++half) {
            const int s = i0 + wm * 32 + mi * 16 + rq + half * 8;
            #pragma unroll
            for (int ni = 0; ni < 4; ++ni) {
                const int d = wn * 32 + ni * 8 + rr;
                float2 o;
                o.x = acc[mi][ni][half * 2 + 0];
                o.y = acc[mi][ni][half * 2 + 1];
                *reinterpret_cast<float2*>(
                    &out[((size_t)(b * SQ + s)) * DM + h * HD + d]) = o;
            }
        }
}

// ---------------------------------------------------------------------------
extern "C" void kernel_launch(void* const* d_in, const int* in_sizes, int n_in,
                              void* d_out, int out_size) {
    const float* query = (const float*)d_in[0];
    const float* key   = (const float*)d_in[1];
    const float* value = (const float*)d_in[2];
    const float* Wq    = (const float*)d_in[3];
    const float* bq    = (const float*)d_in[4];
    const float* Wk    = (const float*)d_in[5];
    const float* bk    = (const float*)d_in[6];
    const float* Wv    = (const float*)d_in[7];
    const float* bv    = (const float*)d_in[8];
    const float* Er    = (const float*)d_in[9];

    float* out  = (float*)d_out;                       // (4,1024,1024)
    float* attn = out + (size_t)NB * SQ * DM;          // (4,16,1024,1024)

    cudaFuncSetAttribute(logits_mma_kernel,
                         cudaFuncAttributeMaxDynamicSharedMemorySize, L_SMEM);
    cudaFuncSetAttribute(proj_mma_kernel,
                         cudaFuncAttributeMaxDynamicSharedMemorySize, P_SMEM);

    const int xn4 = NB * SQ * DM / 4;
    const int wn4 = DM * DM / 4;
    const int en4 = NH * ER_L * HD / 4;
    split_kernel<<<xn4 / 256, 256>>>(query, 0, 0, xn4);
    split_kernel<<<xn4 / 256, 256>>>(key,   1, 0, xn4);
    split_kernel<<<xn4 / 256, 256>>>(value, 2, 0, xn4);
    split_kernel<<<wn4 / 256, 256>>>(Wq, 0, 1, wn4);
    split_kernel<<<wn4 / 256, 256>>>(Wk, 1, 1, wn4);
    split_kernel<<<wn4 / 256, 256>>>(Wv, 2, 1, wn4);
    er_split_kernel<<<(en4 + 255) / 256, 256>>>(Er, en4);
    zero_rowsum_kernel<<<BH, 1024>>>();

    dim3 pg(DM / 128, NB * SQ / 128);
    proj_mma_kernel<<<pg, 256, P_SMEM>>>(0, bq);
    proj_mma_kernel<<<pg, 256, P_SMEM>>>(1, bk);
    proj_mma_kernel<<<pg, 256, P_SMEM>>>(2, bv);

    dim3 lg(SQ / 128, SQ / 128, BH);                   // (8, 8, 64)
    logits_mma_kernel<<<lg, 256, L_SMEM>>>(attn);

    dim3 ag(SQ / 128, BH);                             // (8, 64)
    av_mma_kernel<<<ag, 256>>>(attn, out);
}

// round 15
// speedup vs baseline: 2.4698x; 1.0484x over previous
#include <cuda_runtime.h>
#include <cuda_bf16.h>
#include <math.h>
#include <cstdint>

#define SQ   1024
#define DM   1024
#define NH   16
#define HD   64
#define NB   4
#define BH   (NB*NH)
#define ER_L 2049

// ---------------------------------------------------------------------------
// Device scratch: projected q,k,v stored directly as bf16 hi/lo pairs.
// ---------------------------------------------------------------------------
__device__ __nv_bfloat16 g_qh[(size_t)BH * SQ * HD], g_ql[(size_t)BH * SQ * HD];
__device__ __nv_bfloat16 g_kh[(size_t)BH * SQ * HD], g_kl[(size_t)BH * SQ * HD];
__device__ __nv_bfloat16 g_vh[(size_t)BH * SQ * HD], g_vl[(size_t)BH * SQ * HD];

__device__ __nv_bfloat16 g_xh[3][(size_t)NB * SQ * DM];   // inputs hi
__device__ __nv_bfloat16 g_xl[3][(size_t)NB * SQ * DM];   // inputs lo
__device__ __nv_bfloat16 g_wh[3][(size_t)DM * DM];        // weights hi
__device__ __nv_bfloat16 g_wl[3][(size_t)DM * DM];        // weights lo

__device__ __nv_bfloat16 g_erh[(size_t)NH * ER_L * HD];   // Er hi
__device__ __nv_bfloat16 g_erl[(size_t)NH * ER_L * HD];   // Er lo

__device__ float g_rowsum[(size_t)BH * SQ];               // softmax denominators

// ---------------------------------------------------------------------------
// mma.sync + cp.async helpers
// ---------------------------------------------------------------------------
__device__ __forceinline__ uint32_t smem_u32(const void* p) {
    uint32_t a;
    asm("{ .reg .u64 t; cvta.to.shared.u64 t, %1; cvt.u32.u64 %0, t; }"
        : "=r"(a) : "l"(p));
    return a;
}
__device__ __forceinline__ void ldsm_x4(uint32_t (&r)[4], uint32_t addr) {
    asm volatile("ldmatrix.sync.aligned.m8n8.x4.shared.b16 {%0,%1,%2,%3}, [%4];"
                 : "=r"(r[0]), "=r"(r[1]), "=r"(r[2]), "=r"(r[3]) : "r"(addr));
}
__device__ __forceinline__ void mma_bf16(float (&c)[4], const uint32_t (&a)[4],
                                         const uint32_t b0, const uint32_t b1) {
    asm volatile("mma.sync.aligned.m16n8k16.row.col.f32.bf16.bf16.f32 "
                 "{%0,%1,%2,%3}, {%4,%5,%6,%7}, {%8,%9}, {%0,%1,%2,%3};"
                 : "+f"(c[0]), "+f"(c[1]), "+f"(c[2]), "+f"(c[3])
                 : "r"(a[0]), "r"(a[1]), "r"(a[2]), "r"(a[3]), "r"(b0), "r"(b1));
}
#define CP_ASYNC16(smem, gptr) \
    asm volatile("cp.async.cg.shared.global [%0], [%1], 16;" \
                 :: "r"(smem), "l"(gptr) : "memory")
#define CP_COMMIT() asm volatile("cp.async.commit_group;" ::: "memory")
#define CP_WAIT(n)  asm volatile("cp.async.wait_group %0;" :: "n"(n) : "memory")

__device__ __forceinline__ void f4_to_hilo(float4 v, uint2& H, uint2& L) {
    union { __nv_bfloat16 b[4]; uint2 u; } hh, ll;
    hh.b[0] = __float2bfloat16(v.x);
    hh.b[1] = __float2bfloat16(v.y);
    hh.b[2] = __float2bfloat16(v.z);
    hh.b[3] = __float2bfloat16(v.w);
    ll.b[0] = __float2bfloat16(v.x - __bfloat162float(hh.b[0]));
    ll.b[1] = __float2bfloat16(v.y - __bfloat162float(hh.b[1]));
    ll.b[2] = __float2bfloat16(v.z - __bfloat162float(hh.b[2]));
    ll.b[3] = __float2bfloat16(v.w - __bfloat162float(hh.b[3]));
    H = hh.u; L = ll.u;
}

// ---------------------------------------------------------------------------
// fp32 -> bf16 hi/lo splits
// ---------------------------------------------------------------------------
__global__ __launch_bounds__(256)
void split_kernel(const float* __restrict__ src, int which, int isW, int n4) {
    int i = blockIdx.x * blockDim.x + threadIdx.x;
    if (i >= n4) return;
    __nv_bfloat16* hi = isW ? g_wh[which] : g_xh[which];
    __nv_bfloat16* lo = isW ? g_wl[which] : g_xl[which];
    float4 v = reinterpret_cast<const float4*>(src)[i];
    uint2 H, L;
    f4_to_hilo(v, H, L);
    reinterpret_cast<uint2*>(hi)[i] = H;
    reinterpret_cast<uint2*>(lo)[i] = L;
}

__global__ __launch_bounds__(256)
void er_split_kernel(const float* __restrict__ Er, int n4) {
    int i = blockIdx.x * blockDim.x + threadIdx.x;
    if (i >= n4) return;
    float4 v = reinterpret_cast<const float4*>(Er)[i];
    uint2 H, L;
    f4_to_hilo(v, H, L);
    reinterpret_cast<uint2*>(g_erh)[i] = H;
    reinterpret_cast<uint2*>(g_erl)[i] = L;
}

__global__ __launch_bounds__(1024)
void zero_rowsum_kernel() {
    g_rowsum[blockIdx.x * 1024 + threadIdx.x] = 0.f;
}

// ---------------------------------------------------------------------------
// Projection GEMM on mma.sync; cp.async double-buffered; 3 projections in
// one launch (blockIdx.z selects q/k/v); epilogue writes bf16 hi/lo.
// ---------------------------------------------------------------------------
#define PROW 40
#define P_PLANE (128 * PROW)              // bf16 elements per plane
#define P_SMEM  (2 * 4 * P_PLANE * 2)     // 81920 bytes

__global__ __launch_bounds__(256, 1)
void proj_mma_kernel(const float* __restrict__ bq,
                     const float* __restrict__ bk,
                     const float* __restrict__ bv) {
    extern __shared__ __nv_bfloat16 psm[];   // [2][4][128*PROW]

    const int which = blockIdx.z;
    const float* bias = (which == 0) ? bq : (which == 1) ? bk : bv;
    const __nv_bfloat16* Ah = g_xh[which];
    const __nv_bfloat16* Al = g_xl[which];
    const __nv_bfloat16* Bh = g_wh[which];
    const __nv_bfloat16* Bl = g_wl[which];
    __nv_bfloat16* oh = (which == 0) ? g_qh : (which == 1) ? g_kh : g_vh;
    __nv_bfloat16* ol = (which == 0) ? g_ql : (which == 1) ? g_kl : g_vl;

    const int tid = threadIdx.x;
    const int wid = tid >> 5;
    const int lid = tid & 31;
    const int wm = wid & 1;
    const int wn = wid >> 1;
    const int m0 = blockIdx.y * 128;
    const int n0 = blockIdx.x * 128;

    const int a_row = (lid & 7) + ((lid >> 3) & 1) * 8;
    const int a_kh  = (lid >= 16) ? 8 : 0;
    const int b_n   = (lid & 7) + ((lid >= 16) ? 8 : 0);
    const int b_kh  = ((lid >> 3) & 1) * 8;

    const uint32_t sbase = smem_u32(psm);

    float acc[4][4][4] = {};

    auto load_chunk = [&](int c, int buf) {
        const int k0g = c * 32;
        #pragma unroll
        for (int p = 0; p < 4; ++p) {
            const __nv_bfloat16* g = (p == 0) ? Ah : (p == 1) ? Al
                                    : (p == 2) ? Bh : Bl;
            const int rbase = (p < 2) ? m0 : n0;
            #pragma unroll
            for (int it = 0; it < 2; ++it) {
                int idx = tid + it * 256;        // 0..511
                int r = idx >> 2, seg = idx & 3; // seg: 8 bf16 = 16 B
                uint32_t dst = sbase +
                    (uint32_t)(((buf * 4 + p) * P_PLANE + r * PROW + seg * 8) * 2);
                CP_ASYNC16(dst, g + (size_t)(rbase + r) * DM + k0g + seg * 8);
            }
        }
        CP_COMMIT();
    };

    load_chunk(0, 0);

    const int NCH = DM / 32;
    for (int c = 0; c < NCH; ++c) {
        const int buf = c & 1;
        if (c + 1 < NCH) { load_chunk(c + 1, (c + 1) & 1); CP_WAIT(1); }
        else             { CP_WAIT(0); }
        __syncthreads();

        const uint32_t sA_h = sbase + (uint32_t)((buf * 4 + 0) * P_PLANE * 2);
        const uint32_t sA_l = sbase + (uint32_t)((buf * 4 + 1) * P_PLANE * 2);
        const uint32_t sB_h = sbase + (uint32_t)((buf * 4 + 2) * P_PLANE * 2);
        const uint32_t sB_l = sbase + (uint32_t)((buf * 4 + 3) * P_PLANE * 2);

        #pragma unroll
        for (int ks = 0; ks < 2; ++ks) {
            const int k0 = ks * 16;
            uint32_t fAh[4][4], fAl[4][4], fBh[4][2], fBl[4][2];
            #pragma unroll
            for (int mi = 0; mi < 4; ++mi) {
                uint32_t off = (uint32_t)(((wm * 64 + mi * 16 + a_row) * PROW
                                           + k0 + a_kh) * 2);
                ldsm_x4(fAh[mi], sA_h + off);
                ldsm_x4(fAl[mi], sA_l + off);
            }
            #pragma unroll
            for (int pp = 0; pp < 2; ++pp) {
                uint32_t off = (uint32_t)(((wn * 32 + pp * 16 + b_n) * PROW
                                           + k0 + b_kh) * 2);
                uint32_t t[4];
                ldsm_x4(t, sB_h + off);
                fBh[pp * 2][0] = t[0]; fBh[pp * 2][1] = t[1];
                fBh[pp * 2 + 1][0] = t[2]; fBh[pp * 2 + 1][1] = t[3];
                ldsm_x4(t, sB_l + off);
                fBl[pp * 2][0] = t[0]; fBl[pp * 2][1] = t[1];
                fBl[pp * 2 + 1][0] = t[2]; fBl[pp * 2 + 1][1] = t[3];
            }
            #pragma unroll
            for (int mi = 0; mi < 4; ++mi)
                #pragma unroll
                for (int ni = 0; ni < 4; ++ni) {
                    mma_bf16(acc[mi][ni], fAh[mi], fBh[ni][0], fBh[ni][1]);
                    mma_bf16(acc[mi][ni], fAh[mi], fBl[ni][0], fBl[ni][1]);
                    mma_bf16(acc[mi][ni], fAl[mi], fBh[ni][0], fBh[ni][1]);
                }
        }
        __syncthreads();
    }

    const int rq = lid >> 2, rr = (lid & 3) * 2;
    #pragma unroll
    for (int mi = 0; mi < 4; ++mi) {
        #pragma unroll
        for (int half = 0; half < 2; ++half) {
            const int m = m0 + wm * 64 + mi * 16 + rq + half * 8;
            const int bb = m >> 10, s = m & 1023;
            #pragma unroll
            for (int ni = 0; ni < 4; ++ni) {
                const int n = n0 + wn * 32 + ni * 8 + rr;
                const int h = n >> 6, d = n & 63;
                float ox = acc[mi][ni][half * 2 + 0] + bias[n];
                float oy = acc[mi][ni][half * 2 + 1] + bias[n + 1];
                __nv_bfloat16 hx = __float2bfloat16(ox);
                __nv_bfloat16 hy = __float2bfloat16(oy);
                __nv_bfloat16 lx = __float2bfloat16(ox - __bfloat162float(hx));
                __nv_bfloat16 ly = __float2bfloat16(oy - __bfloat162float(hy));
                size_t o = ((size_t)((bb * NH + h) * SQ + s)) * HD + d;
                *reinterpret_cast<__nv_bfloat162*>(&oh[o]) = __nv_bfloat162(hx, hy);
                *reinterpret_cast<__nv_bfloat162*>(&ol[o]) = __nv_bfloat162(lx, ly);
            }
        }
    }
}

// ---------------------------------------------------------------------------
// Logits + exp + rowsum: 128x128 tile per block.
// Q fragments in registers; B tiles pipelined: Q||Er1 loads concurrent,
// then Er0, then K. Phase order: Er1 (Es cols 128+), Er0 (cols 0+), K.
// attn[b,h,i,j] = exp((q.k + q.Er[1023+j-i]) / 8); rowsum via atomicAdd.
// ---------------------------------------------------------------------------
#define LROW 72
#define L_PLANE (128 * LROW)                 // bf16 per plane
#define L_BUF   (2 * L_PLANE)                // 2 planes (hi+lo)
#define ES_STRIDE 260
#define L_SMEM (2 * L_BUF * 2 + 128 * ES_STRIDE * 4)   // 73728 + 133120 = 206848

__global__ __launch_bounds__(256, 1)
void logits_mma_kernel(float* __restrict__ attn) {
    extern __shared__ char lsm[];
    __nv_bfloat16* Bbuf = reinterpret_cast<__nv_bfloat16*>(lsm);
    float* Es = reinterpret_cast<float*>(lsm + 2 * L_BUF * 2);

    const int bh = blockIdx.z;
    const int h  = bh & 15;
    const int i0 = blockIdx.y * 128;
    const int j0 = blockIdx.x * 128;
    const int l0b = 896 + j0 - i0;           // Er row for t=0; l0b+255 <= 2047

    const __nv_bfloat16* qh = g_qh + (size_t)bh * SQ * HD;
    const __nv_bfloat16* ql = g_ql + (size_t)bh * SQ * HD;
    const __nv_bfloat16* kh = g_kh + (size_t)bh * SQ * HD;
    const __nv_bfloat16* kl = g_kl + (size_t)bh * SQ * HD;
    const __nv_bfloat16* eh = g_erh + (size_t)h * ER_L * HD;
    const __nv_bfloat16* el = g_erl + (size_t)h * ER_L * HD;

    const int tid = threadIdx.x;
    const int wid = tid >> 5;
    const int lid = tid & 31;
    const int wm = wid & 3;
    const int wn = wid >> 2;

    const int a_row = (lid & 7) + ((lid >> 3) & 1) * 8;
    const int a_kh  = (lid >= 16) ? 8 : 0;
    const int b_n   = (lid & 7) + ((lid >= 16) ? 8 : 0);
    const int b_kh  = ((lid >> 3) & 1) * 8;
    const int rq = lid >> 2, rr = (lid & 3) * 2;

    const uint32_t sb = smem_u32(Bbuf);

    auto load_tile = [&](const __nv_bfloat16* pH, const __nv_bfloat16* pL,
                         size_t row0, int buf) {
        #pragma unroll
        for (int it = 0; it < 4; ++it) {
            int idx = tid + it * 256;            // 0..1023
            int r = idx >> 3, seg = idx & 7;     // seg: 8 bf16 = 16 B
            size_t goff = (row0 + r) * HD + seg * 8;
            uint32_t d0 = sb + (uint32_t)((buf * L_BUF + r * LROW + seg * 8) * 2);
            CP_ASYNC16(d0, pH + goff);
            CP_ASYNC16(d0 + (uint32_t)(L_PLANE * 2), pL + goff);
        }
        CP_COMMIT();
    };

    // G0: Q -> buf0  ||  G1: Er chunk1 -> buf1  (concurrent)
    load_tile(qh, ql, (size_t)i0, 0);
    load_tile(eh, el, (size_t)(l0b + 128), 1);
    CP_WAIT(1);                    // Q (G0) done; Er1 may still fly
    __syncthreads();

    uint32_t fQh[4][2][4], fQl[4][2][4];
    #pragma unroll
    for (int ks = 0; ks < 4; ++ks)
        #pragma unroll
        for (int mi = 0; mi < 2; ++mi) {
            uint32_t off = (uint32_t)(((wm * 32 + mi * 16 + a_row) * LROW
                                       + ks * 16 + a_kh) * 2);
            ldsm_x4(fQh[ks][mi], sb + off);
            ldsm_x4(fQl[ks][mi], sb + (uint32_t)(L_PLANE * 2) + off);
        }
    __syncthreads();   // everyone done reading buf0

    // G2: Er chunk0 -> buf0
    load_tile(eh, el, (size_t)l0b, 0);

    float acc[2][8][4];

    // phase 0: Er1 (buf1, Es cols 128..255)
    // phase 1: Er0 (buf0, Es cols 0..127)
    // phase 2: K   (buf1)
    #pragma unroll
    for (int phase = 0; phase < 3; ++phase) {
        if (phase < 2) CP_WAIT(1); else CP_WAIT(0);
        __syncthreads();

        const int buf = (phase == 1) ? 0 : 1;
        const uint32_t bH = sb + (uint32_t)(buf * L_BUF * 2);
        const uint32_t bL = bH + (uint32_t)(L_PLANE * 2);

        #pragma unroll
        for (int mi = 0; mi < 2; ++mi)
            #pragma unroll
            for (int ni = 0; ni < 8; ++ni)
                #pragma unroll
                for (int e = 0; e < 4; ++e) acc[mi][ni][e] = 0.f;

        #pragma unroll
        for (int ks = 0; ks < 4; ++ks) {
            const int k0 = ks * 16;
            uint32_t fBh[8][2], fBl[8][2];
            #pragma unroll
            for (int pp = 0; pp < 4; ++pp) {
                uint32_t off = (uint32_t)(((wn * 64 + pp * 16 + b_n) * LROW
                                           + k0 + b_kh) * 2);
                uint32_t t4[4];
                ldsm_x4(t4, bH + off);
                fBh[pp * 2][0] = t4[0]; fBh[pp * 2][1] = t4[1];
                fBh[pp * 2 + 1][0] = t4[2]; fBh[pp * 2 + 1][1] = t4[3];
                ldsm_x4(t4, bL + off);
                fBl[pp * 2][0] = t4[0]; fBl[pp * 2][1] = t4[1];
                fBl[pp * 2 + 1][0] = t4[2]; fBl[pp * 2 + 1][1] = t4[3];
            }
            #pragma unroll
            for (int mi = 0; mi < 2; ++mi)
                #pragma unroll
                for (int ni = 0; ni < 8; ++ni) {
                    mma_bf16(acc[mi][ni], fQh[ks][mi], fBh[ni][0], fBh[ni][1]);
                    mma_bf16(acc[mi][ni], fQh[ks][mi], fBl[ni][0], fBl[ni][1]);
                    mma_bf16(acc[mi][ni], fQl[ks][mi], fBh[ni][0], fBh[ni][1]);
                }
        }

        if (phase == 0) {
            __syncthreads();                     // all reads of buf1 done
            load_tile(kh, kl, (size_t)j0, 1);    // G3: K -> buf1
        }

        if (phase < 2) {
            const int colbase = (phase == 0) ? 128 : 0;
            #pragma unroll
            for (int mi = 0; mi < 2; ++mi)
                #pragma unroll
                for (int half = 0; half < 2; ++half) {
                    const int row = wm * 32 + mi * 16 + rq + half * 8;
                    #pragma unroll
                    for (int ni = 0; ni < 8; ++ni) {
                        const int col = colbase + wn * 64 + ni * 8 + rr;
                        *reinterpret_cast<float2*>(&Es[row * ES_STRIDE + col]) =
                            make_float2(acc[mi][ni][half * 2], acc[mi][ni][half * 2 + 1]);
                    }
                }
        }
    }

    __syncthreads();   // all Es writes visible

    // epilogue: exp + attn store + row-sum accumulation
    #pragma unroll
    for (int mi = 0; mi < 2; ++mi)
        #pragma unroll
        for (int half = 0; half < 2; ++half) {
            const int ip = wm * 32 + mi * 16 + rq + half * 8;
            const float* EsRow = Es + (size_t)ip * ES_STRIDE + (127 - ip);
            float* arow = attn + ((size_t)bh * SQ + i0 + ip) * SQ + j0;
            float rs = 0.f;
            #pragma unroll
            for (int ni = 0; ni < 8; ++ni) {
                const int jp = wn * 64 + ni * 8 + rr;
                float ex = __expf((acc[mi][ni][half * 2 + 0] + EsRow[jp])     * 0.125f);
                float ey = __expf((acc[mi][ni][half * 2 + 1] + EsRow[jp + 1]) * 0.125f);
                *reinterpret_cast<float2*>(&arow[jp]) = make_float2(ex, ey);
                rs += ex + ey;
            }
            rs += __shfl_xor_sync(0xffffffffu, rs, 1);
            rs += __shfl_xor_sync(0xffffffffu, rs, 2);
            if ((lid & 3) == 0)
                atomicAdd(&g_rowsum[(size_t)bh * SQ + i0 + ip], rs);
        }
}

// ---------------------------------------------------------------------------
// av + softmax normalization: reads exp values, normalizes in place,
// out = P_norm . v.  Block: 128 rows x 64 cols per (b,h).
// ---------------------------------------------------------------------------
#define VROW 72

__global__ __launch_bounds__(256, 2)
void av_mma_kernel(float* __restrict__ attn, float* __restrict__ out) {
    __shared__ __nv_bfloat16 Ph[128 * VROW], Pl[128 * VROW];
    __shared__ __nv_bfloat16 Vh[64 * VROW],  Vl[64 * VROW];
    __shared__ float s_inv[128];

    const int bh = blockIdx.y;
    const int b = bh >> 4, h = bh & 15;
    const int i0 = blockIdx.x * 128;
    float* ab = attn + (size_t)bh * SQ * SQ;
    const __nv_bfloat16* vh = g_vh + (size_t)bh * SQ * HD;
    const __nv_bfloat16* vl = g_vl + (size_t)bh * SQ * HD;

    const int tid = threadIdx.x;
    const int wid = tid >> 5;
    const int lid = tid & 31;
    const int wm = wid & 3;
    const int wn = wid >> 2;

    const int a_row = (lid & 7) + ((lid >> 3) & 1) * 8;
    const int a_kh  = (lid >= 16) ? 8 : 0;
    const int b_n   = (lid & 7) + ((lid >= 16) ? 8 : 0);
    const int b_kh  = ((lid >> 3) & 1) * 8;
    const int rq = lid >> 2, rr = (lid & 3) * 2;

    const uint32_t sPh = smem_u32(Ph), sPl = smem_u32(Pl);
    const uint32_t sVh = smem_u32(Vh), sVl = smem_u32(Vl);

    if (tid < 128)
        s_inv[tid] = 1.0f / g_rowsum[(size_t)bh * SQ + i0 + tid];

    float acc[2][4][4] = {};

    for (int c = 0; c < SQ / 64; ++c) {
        __syncthreads();
        // P tile: load exp values, normalize, write back, convert hi/lo
        #pragma unroll
        for (int it = 0; it < 8; ++it) {
            int idx = tid + it * 256;
            int r = idx >> 4, c4 = idx & 15;
            float* ap = ab + (size_t)(i0 + r) * SQ + c * 64 + c4 * 4;
            float4 v = *reinterpret_cast<const float4*>(ap);
            const float inv = s_inv[r];
            v.x *= inv; v.y *= inv; v.z *= inv; v.w *= inv;
            *reinterpret_cast<float4*>(ap) = v;
            uint2 H, L;
            f4_to_hilo(v, H, L);
            *reinterpret_cast<uint2*>(&Ph[r * VROW + c4 * 4]) = H;
            *reinterpret_cast<uint2*>(&Pl[r * VROW + c4 * 4]) = L;
        }
        // V tile transposed from bf16 hi/lo: smem[d][j]
        #pragma unroll
        for (int it = 0; it < 4; ++it) {
            int idx = tid + it * 256;
            int j = idx >> 4, c4 = idx & 15;
            int d0 = c4 * 4;
            size_t off = (size_t)(c * 64 + j) * HD + d0;
            union { uint2 u; __nv_bfloat16 b[4]; } hv, lv;
            hv.u = *reinterpret_cast<const uint2*>(&vh[off]);
            lv.u = *reinterpret_cast<const uint2*>(&vl[off]);
            #pragma unroll
            for (int x = 0; x < 4; ++x) {
                Vh[(d0 + x) * VROW + j] = hv.b[x];
                Vl[(d0 + x) * VROW + j] = lv.b[x];
            }
        }
        __syncthreads();

        #pragma unroll
        for (int ks = 0; ks < 4; ++ks) {
            const int k0 = ks * 16;
            uint32_t fAh[2][4], fAl[2][4], fBh[4][2], fBl[4][2];
            #pragma unroll
            for (int mi = 0; mi < 2; ++mi) {
                uint32_t off = (uint32_t)(((wm * 32 + mi * 16 + a_row) * VROW
                                           + k0 + a_kh) * 2);
                ldsm_x4(fAh[mi], sPh + off);
                ldsm_x4(fAl[mi], sPl + off);
            }
            #pragma unroll
            for (int pp = 0; pp < 2; ++pp) {
                uint32_t off = (uint32_t)(((wn * 32 + pp * 16 + b_n) * VROW
                                           + k0 + b_kh) * 2);
                uint32_t t4[4];
                ldsm_x4(t4, sVh + off);
                fBh[pp * 2][0] = t4[0]; fBh[pp * 2][1] = t4[1];
                fBh[pp * 2 + 1][0] = t4[2]; fBh[pp * 2 + 1][1] = t4[3];
                ldsm_x4(t4, sVl + off);
                fBl[pp * 2][0] = t4[0]; fBl[pp * 2][1] = t4[1];
                fBl[pp * 2 + 1][0] = t4[2]; fBl[pp * 2 + 1][1] = t4[3];
            }
            #pragma unroll
            for (int mi = 0; mi < 2; ++mi)
                #pragma unroll
                for (int ni = 0; ni < 4; ++ni) {
                    mma_bf16(acc[mi][ni], fAh[mi], fBh[ni][0], fBh[ni][1]);
                    mma_bf16(acc[mi][ni], fAh[mi], fBl[ni][0], fBl[ni][1]);
                    mma_bf16(acc[mi][ni], fAl[mi], fBh[ni][0], fBh[ni][1]);
                }
        }
    }

    #pragma unroll
    for (int mi = 0; mi < 2; ++mi)
        #pragma unroll
        for (int half = 0; half < 2; ++half) {
            const int s = i0 + wm * 32 + mi * 16 + rq + half * 8;
            #pragma unroll
            for (int ni = 0; ni < 4; ++ni) {
                const int d = wn * 32 + ni * 8 + rr;
                float2 o;
                o.x = acc[mi][ni][half * 2 + 0];
                o.y = acc[mi][ni][half * 2 + 1];
                *reinterpret_cast<float2*>(
                    &out[((size_t)(b * SQ + s)) * DM + h * HD + d]) = o;
            }
        }
}

// ---------------------------------------------------------------------------
extern "C" void kernel_launch(void* const* d_in, const int* in_sizes, int n_in,
                              void* d_out, int out_size) {
    const float* query = (const float*)d_in[0];
    const float* key   = (const float*)d_in[1];
    const float* value = (const float*)d_in[2];
    const float* Wq    = (const float*)d_in[3];
    const float* bq    = (const float*)d_in[4];
    const float* Wk    = (const float*)d_in[5];
    const float* bk    = (const float*)d_in[6];
    const float* Wv    = (const float*)d_in[7];
    const float* bv    = (const float*)d_in[8];
    const float* Er    = (const float*)d_in[9];

    float* out  = (float*)d_out;                       // (4,1024,1024)
    float* attn = out + (size_t)NB * SQ * DM;          // (4,16,1024,1024)

    cudaFuncSetAttribute(logits_mma_kernel,
                         cudaFuncAttributeMaxDynamicSharedMemorySize, L_SMEM);
    cudaFuncSetAttribute(proj_mma_kernel,
                         cudaFuncAttributeMaxDynamicSharedMemorySize, P_SMEM);

    const int xn4 = NB * SQ * DM / 4;
    const int wn4 = DM * DM / 4;
    const int en4 = NH * ER_L * HD / 4;
    split_kernel<<<xn4 / 256, 256>>>(query, 0, 0, xn4);
    split_kernel<<<xn4 / 256, 256>>>(key,   1, 0, xn4);
    split_kernel<<<xn4 / 256, 256>>>(value, 2, 0, xn4);
    split_kernel<<<wn4 / 256, 256>>>(Wq, 0, 1, wn4);
    split_kernel<<<wn4 / 256, 256>>>(Wk, 1, 1, wn4);
    split_kernel<<<wn4 / 256, 256>>>(Wv, 2, 1, wn4);
    er_split_kernel<<<(en4 + 255) / 256, 256>>>(Er, en4);
    zero_rowsum_kernel<<<BH, 1024>>>();

    dim3 pg(DM / 128, NB * SQ / 128, 3);               // (8, 32, 3)
    proj_mma_kernel<<<pg, 256, P_SMEM>>>(bq, bk, bv);

    dim3 lg(SQ / 128, SQ / 128, BH);                   // (8, 8, 64)
    logits_mma_kernel<<<lg, 256, L_SMEM>>>(attn);

    dim3 ag(SQ / 128, BH);                             // (8, 64)
    av_mma_kernel<<<ag, 256>>>(attn, out);
}